// round 11
// baseline (speedup 1.0000x reference)
#include <cuda_runtime.h>
#include <math.h>

#define BATCH 4096
#define NCLS  1000

// ---------------- scratch (device globals; no dynamic allocation) ----------------
__device__ float g_h1[BATCH*32*16*16];   // conv1 pooled out  [B,32,16,16]
__device__ float g_h2[BATCH*64*8*8];     // conv2 pooled out  [B,64,8,8]
__device__ float g_h3[BATCH*2048];       // conv3 pooled flat [B,2048]
__device__ float g_feat[BATCH*256];      // fc out            [B,256]
__device__ float g_y[BATCH*256];         // layernorm out     [B,256]
__device__ int   g_tidx[BATCH*2];        // top2 expert idx
__device__ float g_tg[BATCH*2];          // top2 gate weights
__device__ float g_gatesum[16];
__device__ int   g_counts[16];
__device__ int   g_offsets[16];
__device__ int   g_cursor[16];
__device__ int   g_list_b[BATCH*2];      // token id per grouped slot
__device__ float g_list_g[BATCH*2];      // gate weight per grouped slot
__device__ int   g_slotpos[BATCH*2];     // (b,k) -> grouped slot
__device__ float g_h1e[BATCH*2*1024];    // expert hidden per slot
__device__ float g_eo[BATCH*2*256];      // gate-scaled expert out per slot
// conv weights transposed to [tap][ci][oc], split hi/lo tf32
__device__ float g_wt2hi[9*32*64];
__device__ float g_wt2lo[9*32*64];
__device__ float g_wt3hi[9*64*128];
__device__ float g_wt3lo[9*64*128];
// expert weights split hi/lo (layout already [e][k][n])
__device__ float g_e1hi[16*262144];
__device__ float g_e1lo[16*262144];
__device__ float g_e2hi[16*262144];
__device__ float g_e2lo[16*262144];
// fc + out weights split hi/lo (ow padded to [256][1024])
__device__ float g_fchi[2048*256];
__device__ float g_fclo[2048*256];
__device__ float g_owhi[256*1024];
__device__ float g_owlo[256*1024];

// ---------------- tf32 helpers ----------------
__device__ __forceinline__ float tf32_hi(float x) {
    return __uint_as_float(__float_as_uint(x) & 0xFFFFE000u);
}

__device__ __forceinline__ void mma_tf32(float* c, const unsigned* a, const unsigned* b) {
    asm volatile(
        "mma.sync.aligned.m16n8k8.row.col.f32.tf32.tf32.f32 "
        "{%0,%1,%2,%3}, {%4,%5,%6,%7}, {%8,%9}, {%0,%1,%2,%3};"
        : "+f"(c[0]), "+f"(c[1]), "+f"(c[2]), "+f"(c[3])
        : "r"(a[0]), "r"(a[1]), "r"(a[2]), "r"(a[3]), "r"(b[0]), "r"(b[1]));
}

// ---------------- init ----------------
__global__ void k_zero() {
    int t = threadIdx.x;
    if (t < 16) { g_gatesum[t] = 0.f; g_counts[t] = 0; }
}

// ---------------- weight transpose: OIHW -> [tap][ci][oc], hi/lo split ----------------
__global__ void k_wtrans(const float* __restrict__ c2w, const float* __restrict__ c3w) {
    int idx = blockIdx.x*256 + threadIdx.x;
    if (idx < 18432) {          // conv2: [64][32][9]
        int oc = idx / 288, rem = idx % 288;
        int ci = rem / 9, t = rem % 9;
        float v = c2w[idx];
        float hi = tf32_hi(v);
        int d = (t*32 + ci)*64 + oc;
        g_wt2hi[d] = hi; g_wt2lo[d] = v - hi;
    }
    if (idx < 73728) {          // conv3: [128][64][9]
        int oc = idx / 576, rem = idx % 576;
        int ci = rem / 9, t = rem % 9;
        float v = c3w[idx];
        float hi = tf32_hi(v);
        int d = (t*64 + ci)*128 + oc;
        g_wt3hi[d] = hi; g_wt3lo[d] = v - hi;
    }
}

// ---------------- expert weight hi/lo split ----------------
__global__ void k_wprep(const float* __restrict__ w1, const float* __restrict__ w2) {
    for (int i = blockIdx.x*256 + threadIdx.x; i < 16*262144; i += gridDim.x*256) {
        float v = w1[i]; float h = tf32_hi(v);
        g_e1hi[i] = h; g_e1lo[i] = v - h;
        v = w2[i]; h = tf32_hi(v);
        g_e2hi[i] = h; g_e2lo[i] = v - h;
    }
}

// ---------------- fc + out weight hi/lo split (ow padded 1000->1024) ----------------
__global__ void k_wprep2(const float* __restrict__ fcw, const float* __restrict__ ow) {
    int i = blockIdx.x*256 + threadIdx.x;
    if (i < 2048*256) {
        float v = fcw[i]; float h = tf32_hi(v);
        g_fchi[i] = h; g_fclo[i] = v - h;
    }
    if (i < 256*1024) {
        int k = i >> 10, n = i & 1023;
        float v = (n < NCLS) ? ow[k*NCLS + n] : 0.f;
        float h = tf32_hi(v);
        g_owhi[i] = h; g_owlo[i] = v - h;
    }
}

// ---------------- conv1: [B,3,32,32] -> pool -> relu -> [B,32,16,16] (2 img/block, fp32) ----------------
__global__ void __launch_bounds__(512) k_conv1(const float* __restrict__ x,
                                               const float* __restrict__ w,
                                               const float* __restrict__ bias) {
    __shared__ float xs[2*3*34*34];
    __shared__ float ws[27*36];
    __shared__ float bs[32];
    const int b0 = blockIdx.x*2, tid = threadIdx.x;
    for (int i = tid; i < 2*3468; i += 512) xs[i] = 0.f;
    if (tid < 32) bs[tid] = bias[tid];
    __syncthreads();
    for (int i = tid; i < 2*3072; i += 512) {
        int img = i / 3072, rem = i % 3072;
        int ci = rem >> 10, r2 = rem & 1023;
        xs[img*3468 + ci*1156 + ((r2>>5)+1)*34 + (r2&31) + 1] = x[(b0+img)*3072 + rem];
    }
    for (int i = tid; i < 864; i += 512)
        ws[(i%27)*36 + (i/27)] = w[i];
    __syncthreads();

    const int img = tid >> 8, t = tid & 255;
    const int py = t >> 4, px = t & 15;
    const float* xsI = xs + img*3468;
    float* outp = g_h1 + (b0+img)*8192;
    for (int cb = 0; cb < 32; cb += 8) {
        float acc[8][4];
        #pragma unroll
        for (int j = 0; j < 8; j++) { acc[j][0]=acc[j][1]=acc[j][2]=acc[j][3]=0.f; }
        #pragma unroll
        for (int ci = 0; ci < 3; ci++) {
            #pragma unroll
            for (int ky = 0; ky < 3; ky++) {
                #pragma unroll
                for (int kx = 0; kx < 3; kx++) {
                    const int kk = ci*9 + ky*3 + kx;
                    float wv[8];
                    *(float4*)&wv[0] = *(const float4*)&ws[kk*36 + cb];
                    *(float4*)&wv[4] = *(const float4*)&ws[kk*36 + cb + 4];
                    float iv[4];
                    #pragma unroll
                    for (int dy = 0; dy < 2; dy++)
                        #pragma unroll
                        for (int dx = 0; dx < 2; dx++)
                            iv[dy*2+dx] = xsI[ci*1156 + (2*py+dy+ky)*34 + (2*px+dx+kx)];
                    #pragma unroll
                    for (int j = 0; j < 8; j++)
                        #pragma unroll
                        for (int p = 0; p < 4; p++)
                            acc[j][p] += wv[j]*iv[p];
                }
            }
        }
        #pragma unroll
        for (int j = 0; j < 8; j++) {
            float m = fmaxf(fmaxf(acc[j][0],acc[j][1]), fmaxf(acc[j][2],acc[j][3]));
            outp[(cb+j)*256 + t] = fmaxf(m + bs[cb+j], 0.f);
        }
    }
}

// ---------------- conv2: tensor-core 3xTF32 tap-GEMM ----------------
#define C2_SMEM (2*10368*4)
__global__ void __launch_bounds__(256) k_conv2t(const float* __restrict__ bias) {
    extern __shared__ float sm[];
    float* in_hi = sm;
    float* in_lo = sm + 10368;
    const int b = blockIdx.x, tid = threadIdx.x;
    for (int i = tid; i < 10368; i += 256) { in_hi[i] = 0.f; in_lo[i] = 0.f; }
    __syncthreads();
    for (int i = tid; i < 8192; i += 256) {
        int ci = i >> 8, r2 = i & 255;
        float v = g_h1[b*8192 + i];
        float hi = tf32_hi(v);
        int d = ci*324 + ((r2>>4)+1)*18 + (r2&15) + 1;
        in_hi[d] = hi; in_lo[d] = v - hi;
    }
    __syncthreads();

    const int lane = tid & 31, wrp = tid >> 5;
    const int g = lane >> 2, tig = lane & 3;
    const int ocg = wrp >> 2, posg = wrp & 3;
    const int y0 = posg*4;
    const int ocm = ocg*32;

    float c[2][8][4];
    #pragma unroll
    for (int m = 0; m < 2; m++)
        #pragma unroll
        for (int nt = 0; nt < 8; nt++)
            #pragma unroll
            for (int k = 0; k < 4; k++) c[m][nt][k] = 0.f;

    const int blane = tig*324 + g;
    const int wlane = tig*64 + ocm + g;

    for (int c8 = 0; c8 < 32; c8 += 8) {
        #pragma unroll
        for (int t = 0; t < 9; t++) {
            const int ky = t/3, kx = t%3;
            const int wbase = (t*32 + c8)*64 + wlane;
            unsigned ah[2][4], al[2][4];
            #pragma unroll
            for (int m = 0; m < 2; m++) {
                const int wb = wbase + m*16;
                ah[m][0] = __float_as_uint(__ldg(&g_wt2hi[wb]));
                ah[m][1] = __float_as_uint(__ldg(&g_wt2hi[wb+8]));
                ah[m][2] = __float_as_uint(__ldg(&g_wt2hi[wb+256]));
                ah[m][3] = __float_as_uint(__ldg(&g_wt2hi[wb+264]));
                al[m][0] = __float_as_uint(__ldg(&g_wt2lo[wb]));
                al[m][1] = __float_as_uint(__ldg(&g_wt2lo[wb+8]));
                al[m][2] = __float_as_uint(__ldg(&g_wt2lo[wb+256]));
                al[m][3] = __float_as_uint(__ldg(&g_wt2lo[wb+264]));
            }
            const int bstep = c8*324 + blane + kx;
            #pragma unroll
            for (int nt = 0; nt < 8; nt++) {
                const int ry = nt >> 1, xh = nt & 1;
                const int ba = bstep + (y0+ry+ky)*18 + xh*8;
                unsigned bh[2], bl[2];
                bh[0] = __float_as_uint(in_hi[ba]);
                bh[1] = __float_as_uint(in_hi[ba + 4*324]);
                bl[0] = __float_as_uint(in_lo[ba]);
                bl[1] = __float_as_uint(in_lo[ba + 4*324]);
                #pragma unroll
                for (int m = 0; m < 2; m++) {
                    mma_tf32(c[m][nt], ah[m], bh);
                    mma_tf32(c[m][nt], ah[m], bl);
                    mma_tf32(c[m][nt], al[m], bh);
                }
            }
        }
    }

    float* outp = g_h2 + b*4096;
    #pragma unroll
    for (int m = 0; m < 2; m++) {
        #pragma unroll
        for (int h = 0; h < 2; h++) {
            const int oc = ocm + m*16 + h*8 + g;
            const float bv = __ldg(&bias[oc]);
            const int k0 = h*2;
            #pragma unroll
            for (int pr = 0; pr < 2; pr++) {
                #pragma unroll
                for (int xh = 0; xh < 2; xh++) {
                    const int nta = (2*pr)*2 + xh, ntb = nta + 2;
                    float v = fmaxf(fmaxf(c[m][nta][k0], c[m][nta][k0+1]),
                                    fmaxf(c[m][ntb][k0], c[m][ntb][k0+1]));
                    outp[oc*64 + (posg*2+pr)*8 + xh*4 + tig] = fmaxf(v + bv, 0.f);
                }
            }
        }
    }
}

// ---------------- conv3: tensor-core 3xTF32 tap-GEMM ----------------
#define C3_SMEM (2*6400*2*4)
__global__ void __launch_bounds__(256) k_conv3t(const float* __restrict__ bias) {
    extern __shared__ float sm[];
    const int b0 = blockIdx.x*2, tid = threadIdx.x;
    for (int i = tid; i < 12800; i += 256) { sm[i] = 0.f; sm[12800 + i] = 0.f; }
    __syncthreads();
    for (int i = tid; i < 8192; i += 256) {
        int img = i >> 12, rem = i & 4095;
        int ci = rem >> 6, r2 = rem & 63;
        float v = g_h2[(b0+img)*4096 + rem];
        float hi = tf32_hi(v);
        int d = img*6400 + ci*100 + ((r2>>3)+1)*10 + (r2&7) + 1;
        sm[d] = hi; sm[12800 + d] = v - hi;
    }
    __syncthreads();

    const int lane = tid & 31, wrp = tid >> 5;
    const int g = lane >> 2, tig = lane & 3;
    const int img = wrp >> 2, ocg = wrp & 3;
    const int ocm = ocg*32;
    const float* in_hi = sm + img*6400;
    const float* in_lo = sm + 12800 + img*6400;

    float c[2][8][4];
    #pragma unroll
    for (int m = 0; m < 2; m++)
        #pragma unroll
        for (int nt = 0; nt < 8; nt++)
            #pragma unroll
            for (int k = 0; k < 4; k++) c[m][nt][k] = 0.f;

    const int blane = tig*100 + g;
    const int wlane = tig*128 + ocm + g;

    for (int c8 = 0; c8 < 64; c8 += 8) {
        #pragma unroll
        for (int t = 0; t < 9; t++) {
            const int ky = t/3, kx = t%3;
            const int wbase = (t*64 + c8)*128 + wlane;
            unsigned ah[2][4], al[2][4];
            #pragma unroll
            for (int m = 0; m < 2; m++) {
                const int wb = wbase + m*16;
                ah[m][0] = __float_as_uint(__ldg(&g_wt3hi[wb]));
                ah[m][1] = __float_as_uint(__ldg(&g_wt3hi[wb+8]));
                ah[m][2] = __float_as_uint(__ldg(&g_wt3hi[wb+512]));
                ah[m][3] = __float_as_uint(__ldg(&g_wt3hi[wb+520]));
                al[m][0] = __float_as_uint(__ldg(&g_wt3lo[wb]));
                al[m][1] = __float_as_uint(__ldg(&g_wt3lo[wb+8]));
                al[m][2] = __float_as_uint(__ldg(&g_wt3lo[wb+512]));
                al[m][3] = __float_as_uint(__ldg(&g_wt3lo[wb+520]));
            }
            const int bstep = c8*100 + blane + kx;
            #pragma unroll
            for (int nt = 0; nt < 8; nt++) {
                const int ba = bstep + (nt+ky)*10;
                unsigned bh[2], bl[2];
                bh[0] = __float_as_uint(in_hi[ba]);
                bh[1] = __float_as_uint(in_hi[ba + 4*100]);
                bl[0] = __float_as_uint(in_lo[ba]);
                bl[1] = __float_as_uint(in_lo[ba + 4*100]);
                #pragma unroll
                for (int m = 0; m < 2; m++) {
                    mma_tf32(c[m][nt], ah[m], bh);
                    mma_tf32(c[m][nt], ah[m], bl);
                    mma_tf32(c[m][nt], al[m], bh);
                }
            }
        }
    }

    float* outp = g_h3 + (b0+img)*2048;
    #pragma unroll
    for (int m = 0; m < 2; m++) {
        #pragma unroll
        for (int h = 0; h < 2; h++) {
            const int oc = ocm + m*16 + h*8 + g;
            const float bv = __ldg(&bias[oc]);
            const int k0 = h*2;
            #pragma unroll
            for (int py = 0; py < 4; py++) {
                float v = fmaxf(fmaxf(c[m][2*py][k0], c[m][2*py][k0+1]),
                                fmaxf(c[m][2*py+1][k0], c[m][2*py+1][k0+1]));
                outp[oc*16 + py*4 + tig] = fmaxf(v + bv, 0.f);
            }
        }
    }
}

// ---------------- fc (MMA): feat = h3 @ fcw + fcb ----------------
// 64 tokens/block, 8 warps = 2mg x 4ng, K=2048 via 8 smem stages, N=256.
#define GE_SMEM (2*256*68*4)
__global__ void __launch_bounds__(256) k_fcm(const float* __restrict__ fcb) {
    const int bt = blockIdx.x*64;
    extern __shared__ float sm[];
    float* smh = sm;
    float* sml = sm + 256*68;
    const int tid = threadIdx.x;
    const int lane = tid & 31, wrp = tid >> 5;
    const int g = lane >> 2, tig = lane & 3;
    const int mg = wrp >> 2, ng = wrp & 3;

    float c[2][8][4];
    #pragma unroll
    for (int mm = 0; mm < 2; mm++)
        #pragma unroll
        for (int nt = 0; nt < 8; nt++)
            #pragma unroll
            for (int k = 0; k < 4; k++) c[mm][nt][k] = 0.f;

    for (int st = 0; st < 8; st++) {
        __syncthreads();
        for (int i = tid; i < 64*256; i += 256) {
            int rr = i >> 8, cc = i & 255;
            float v = g_h3[(bt+rr)*2048 + st*256 + cc];
            float h = tf32_hi(v);
            smh[cc*68 + rr] = h; sml[cc*68 + rr] = v - h;
        }
        __syncthreads();
        for (int k8 = 0; k8 < 256; k8 += 8) {
            unsigned ah[2][4], al[2][4];
            #pragma unroll
            for (int mm = 0; mm < 2; mm++) {
                const int mb = mg*32 + mm*16 + g;
                const int a0 = (k8+tig)*68 + mb;
                const int a1 = (k8+tig+4)*68 + mb;
                ah[mm][0] = __float_as_uint(smh[a0]);
                ah[mm][1] = __float_as_uint(smh[a0+8]);
                ah[mm][2] = __float_as_uint(smh[a1]);
                ah[mm][3] = __float_as_uint(smh[a1+8]);
                al[mm][0] = __float_as_uint(sml[a0]);
                al[mm][1] = __float_as_uint(sml[a0+8]);
                al[mm][2] = __float_as_uint(sml[a1]);
                al[mm][3] = __float_as_uint(sml[a1+8]);
            }
            #pragma unroll
            for (int nt = 0; nt < 8; nt++) {
                const int col = ng*64 + nt*8 + g;
                const int kb = (st*256 + k8 + tig)*256 + col;
                unsigned bh[2], bl[2];
                bh[0] = __float_as_uint(__ldg(&g_fchi[kb]));
                bh[1] = __float_as_uint(__ldg(&g_fchi[kb + 4*256]));
                bl[0] = __float_as_uint(__ldg(&g_fclo[kb]));
                bl[1] = __float_as_uint(__ldg(&g_fclo[kb + 4*256]));
                #pragma unroll
                for (int mm = 0; mm < 2; mm++) {
                    mma_tf32(c[mm][nt], ah[mm], bh);
                    mma_tf32(c[mm][nt], ah[mm], bl);
                    mma_tf32(c[mm][nt], al[mm], bh);
                }
            }
        }
    }
    #pragma unroll
    for (int mm = 0; mm < 2; mm++)
        #pragma unroll
        for (int h = 0; h < 2; h++) {
            const int row = mg*32 + mm*16 + h*8 + g;
            #pragma unroll
            for (int nt = 0; nt < 8; nt++) {
                const int col = ng*64 + nt*8 + tig*2;
                g_feat[(bt+row)*256 + col]   = c[mm][nt][h*2]   + __ldg(&fcb[col]);
                g_feat[(bt+row)*256 + col+1] = c[mm][nt][h*2+1] + __ldg(&fcb[col+1]);
            }
        }
}

// ---------------- gate: logits, top-2, softmax, counts ----------------
__global__ void __launch_bounds__(256) k_gate(const float* __restrict__ gw,
                                              const float* __restrict__ gb) {
    __shared__ float fs[16*256];
    __shared__ float ls[16*17];
    const int b0 = blockIdx.x*16, tid = threadIdx.x;
    for (int i = tid; i < 4096; i += 256) fs[i] = g_feat[b0*256 + i];
    __syncthreads();
    const int t = tid >> 4, e = tid & 15;
    float acc = gb[e];
    for (int d = 0; d < 256; d++) acc += fs[t*256+d]*__ldg(&gw[d*16+e]);
    ls[t*17+e] = acc;
    __syncthreads();
    if (e == 0) {
        const float* l = &ls[t*17];
        int i1 = 0; float v1 = l[0];
        #pragma unroll
        for (int i = 1; i < 16; i++) if (l[i] > v1) { v1 = l[i]; i1 = i; }
        int i2 = -1; float v2 = -1e30f;
        #pragma unroll
        for (int i = 0; i < 16; i++) if (i != i1 && l[i] > v2) { v2 = l[i]; i2 = i; }
        float e2 = expf(v2 - v1);
        float inv = 1.0f/(1.0f + e2);
        float g1 = inv, g2 = e2*inv;
        int b = b0 + t;
        g_tidx[b*2] = i1;  g_tidx[b*2+1] = i2;
        g_tg[b*2]   = g1;  g_tg[b*2+1]   = g2;
        atomicAdd(&g_gatesum[i1], g1);
        atomicAdd(&g_gatesum[i2], g2);
        atomicAdd(&g_counts[i1], 1);
        atomicAdd(&g_counts[i2], 1);
    }
}

// ---------------- scan offsets + lb_loss ----------------
__global__ void k_scan(float* d_out, int out_size) {
    if (threadIdx.x == 0) {
        int off = 0;
        for (int e = 0; e < 16; e++) {
            g_offsets[e] = off; g_cursor[e] = off; off += g_counts[e];
        }
        float loss = 0.f;
        for (int e = 0; e < 16; e++) {
            float di = g_gatesum[e] / (float)BATCH;
            loss += di * logf(di + 1e-8f);
        }
        if (out_size > BATCH*NCLS) d_out[BATCH*NCLS] = loss;
    }
}

// ---------------- scatter tokens into expert-grouped lists ----------------
__global__ void k_scatter() {
    int s = blockIdx.x*256 + threadIdx.x;
    int e = g_tidx[s];
    int pos = atomicAdd(&g_cursor[e], 1);
    g_list_b[pos] = s >> 1;
    g_list_g[pos] = g_tg[s];
    g_slotpos[s] = pos;
}

// ---------------- expert pass A (MMA): h1 = relu(feat @ w1 + b1) ----------------
__global__ void __launch_bounds__(256) k_e1m(const float* __restrict__ b1) {
    const int e = blockIdx.y;
    const int cnt = g_counts[e];
    const int ts = blockIdx.x*64;
    if (ts >= cnt) return;
    const int off = g_offsets[e];
    const int rows = min(64, cnt - ts);
    extern __shared__ float sm[];
    float* smh = sm;
    float* sml = sm + 256*68;
    const int tid = threadIdx.x;
    for (int i = tid; i < 64*256; i += 256) {
        int rr = i >> 8, cc = i & 255;
        float v = (rr < rows) ? g_feat[g_list_b[off+ts+rr]*256 + cc] : 0.f;
        float h = tf32_hi(v);
        smh[cc*68 + rr] = h; sml[cc*68 + rr] = v - h;
    }
    __syncthreads();
    const int lane = tid & 31, wrp = tid >> 5;
    const int g = lane >> 2, tig = lane & 3;
    const int mg = wrp >> 2, ng = wrp & 3;
    const float* Whi = g_e1hi + e*262144;
    const float* Wlo = g_e1lo + e*262144;

    for (int np = 0; np < 4; np++) {
        const int ncol = np*256 + ng*64;
        float c[2][8][4];
        #pragma unroll
        for (int mm = 0; mm < 2; mm++)
            #pragma unroll
            for (int nt = 0; nt < 8; nt++)
                #pragma unroll
                for (int k = 0; k < 4; k++) c[mm][nt][k] = 0.f;
        for (int k8 = 0; k8 < 256; k8 += 8) {
            unsigned ah[2][4], al[2][4];
            #pragma unroll
            for (int mm = 0; mm < 2; mm++) {
                const int mb = mg*32 + mm*16 + g;
                const int a0 = (k8+tig)*68 + mb;
                const int a1 = (k8+tig+4)*68 + mb;
                ah[mm][0] = __float_as_uint(smh[a0]);
                ah[mm][1] = __float_as_uint(smh[a0+8]);
                ah[mm][2] = __float_as_uint(smh[a1]);
                ah[mm][3] = __float_as_uint(smh[a1+8]);
                al[mm][0] = __float_as_uint(sml[a0]);
                al[mm][1] = __float_as_uint(sml[a0+8]);
                al[mm][2] = __float_as_uint(sml[a1]);
                al[mm][3] = __float_as_uint(sml[a1+8]);
            }
            #pragma unroll
            for (int nt = 0; nt < 8; nt++) {
                const int col = ncol + nt*8 + g;
                const int kb = (k8+tig)*1024 + col;
                unsigned bh[2], bl[2];
                bh[0] = __float_as_uint(__ldg(&Whi[kb]));
                bh[1] = __float_as_uint(__ldg(&Whi[kb + 4*1024]));
                bl[0] = __float_as_uint(__ldg(&Wlo[kb]));
                bl[1] = __float_as_uint(__ldg(&Wlo[kb + 4*1024]));
                #pragma unroll
                for (int mm = 0; mm < 2; mm++) {
                    mma_tf32(c[mm][nt], ah[mm], bh);
                    mma_tf32(c[mm][nt], ah[mm], bl);
                    mma_tf32(c[mm][nt], al[mm], bh);
                }
            }
        }
        #pragma unroll
        for (int mm = 0; mm < 2; mm++)
            #pragma unroll
            for (int h = 0; h < 2; h++) {
                const int row = mg*32 + mm*16 + h*8 + g;
                if (row < rows) {
                    const int slot = off + ts + row;
                    #pragma unroll
                    for (int nt = 0; nt < 8; nt++) {
                        const int col = ncol + nt*8 + tig*2;
                        float v0 = c[mm][nt][h*2]   + __ldg(&b1[e*1024+col]);
                        float v1 = c[mm][nt][h*2+1] + __ldg(&b1[e*1024+col+1]);
                        g_h1e[slot*1024 + col]   = fmaxf(v0, 0.f);
                        g_h1e[slot*1024 + col+1] = fmaxf(v1, 0.f);
                    }
                }
            }
    }
}

// ---------------- expert pass B (MMA): eo = gate*(h1 @ w2 + b2) ----------------
__global__ void __launch_bounds__(256) k_e2m(const float* __restrict__ b2) {
    const int e = blockIdx.y;
    const int cnt = g_counts[e];
    const int ts = blockIdx.x*64;
    if (ts >= cnt) return;
    const int off = g_offsets[e];
    const int rows = min(64, cnt - ts);
    extern __shared__ float sm[];
    float* smh = sm;
    float* sml = sm + 256*68;
    const int tid = threadIdx.x;
    const int lane = tid & 31, wrp = tid >> 5;
    const int g = lane >> 2, tig = lane & 3;
    const int mg = wrp >> 2, ng = wrp & 3;
    const float* Whi = g_e2hi + e*262144;
    const float* Wlo = g_e2lo + e*262144;

    float c[2][8][4];
    #pragma unroll
    for (int mm = 0; mm < 2; mm++)
        #pragma unroll
        for (int nt = 0; nt < 8; nt++)
            #pragma unroll
            for (int k = 0; k < 4; k++) c[mm][nt][k] = 0.f;

    for (int st = 0; st < 4; st++) {
        __syncthreads();
        for (int i = tid; i < 64*256; i += 256) {
            int rr = i >> 8, cc = i & 255;
            float v = (rr < rows) ? g_h1e[(off+ts+rr)*1024 + st*256 + cc] : 0.f;
            float h = tf32_hi(v);
            smh[cc*68 + rr] = h; sml[cc*68 + rr] = v - h;
        }
        __syncthreads();
        for (int k8 = 0; k8 < 256; k8 += 8) {
            unsigned ah[2][4], al[2][4];
            #pragma unroll
            for (int mm = 0; mm < 2; mm++) {
                const int mb = mg*32 + mm*16 + g;
                const int a0 = (k8+tig)*68 + mb;
                const int a1 = (k8+tig+4)*68 + mb;
                ah[mm][0] = __float_as_uint(smh[a0]);
                ah[mm][1] = __float_as_uint(smh[a0+8]);
                ah[mm][2] = __float_as_uint(smh[a1]);
                ah[mm][3] = __float_as_uint(smh[a1+8]);
                al[mm][0] = __float_as_uint(sml[a0]);
                al[mm][1] = __float_as_uint(sml[a0+8]);
                al[mm][2] = __float_as_uint(sml[a1]);
                al[mm][3] = __float_as_uint(sml[a1+8]);
            }
            #pragma unroll
            for (int nt = 0; nt < 8; nt++) {
                const int col = ng*64 + nt*8 + g;
                const int kb = (st*256 + k8 + tig)*256 + col;
                unsigned bh[2], bl[2];
                bh[0] = __float_as_uint(__ldg(&Whi[kb]));
                bh[1] = __float_as_uint(__ldg(&Whi[kb + 4*256]));
                bl[0] = __float_as_uint(__ldg(&Wlo[kb]));
                bl[1] = __float_as_uint(__ldg(&Wlo[kb + 4*256]));
                #pragma unroll
                for (int mm = 0; mm < 2; mm++) {
                    mma_tf32(c[mm][nt], ah[mm], bh);
                    mma_tf32(c[mm][nt], ah[mm], bl);
                    mma_tf32(c[mm][nt], al[mm], bh);
                }
            }
        }
    }
    #pragma unroll
    for (int mm = 0; mm < 2; mm++)
        #pragma unroll
        for (int h = 0; h < 2; h++) {
            const int row = mg*32 + mm*16 + h*8 + g;
            if (row < rows) {
                const int slot = off + ts + row;
                const float gt = g_list_g[slot];
                #pragma unroll
                for (int nt = 0; nt < 8; nt++) {
                    const int col = ng*64 + nt*8 + tig*2;
                    float v0 = c[mm][nt][h*2]   + __ldg(&b2[e*256+col]);
                    float v1 = c[mm][nt][h*2+1] + __ldg(&b2[e*256+col+1]);
                    g_eo[slot*256 + col]   = gt*v0;
                    g_eo[slot*256 + col+1] = gt*v1;
                }
            }
        }
}

// ---------------- combine + residual + LayerNorm ----------------
__global__ void __launch_bounds__(256) k_ln(const float* __restrict__ lng,
                                            const float* __restrict__ lnb) {
    const int b = blockIdx.x, tid = threadIdx.x;
    const int p0 = g_slotpos[b*2], p1 = g_slotpos[b*2+1];
    float y = g_eo[p0*256+tid] + g_eo[p1*256+tid] + g_feat[b*256+tid];
    __shared__ float red[16];
    __shared__ float mu_s, rstd_s;
    float s = y, s2 = y*y;
    #pragma unroll
    for (int o = 16; o > 0; o >>= 1) {
        s  += __shfl_xor_sync(0xffffffffu, s,  o);
        s2 += __shfl_xor_sync(0xffffffffu, s2, o);
    }
    if ((tid & 31) == 0) { red[tid>>5] = s; red[8 + (tid>>5)] = s2; }
    __syncthreads();
    if (tid == 0) {
        float S = 0.f, S2 = 0.f;
        #pragma unroll
        for (int i = 0; i < 8; i++) { S += red[i]; S2 += red[8+i]; }
        float mu = S/256.f;
        mu_s = mu;
        rstd_s = rsqrtf(S2/256.f - mu*mu + 1e-5f);
    }
    __syncthreads();
    g_y[b*256+tid] = (y - mu_s)*rstd_s*lng[tid] + lnb[tid];
}

// ---------------- output projection (MMA): out = y @ ow + ob ----------------
// 64 tokens/block, K=256 single stage, N=1024 padded via 4 passes, guard col<1000.
__global__ void __launch_bounds__(256) k_outm(const float* __restrict__ ob,
                                              float* __restrict__ out) {
    const int bt = blockIdx.x*64;
    extern __shared__ float sm[];
    float* smh = sm;
    float* sml = sm + 256*68;
    const int tid = threadIdx.x;
    for (int i = tid; i < 64*256; i += 256) {
        int rr = i >> 8, cc = i & 255;
        float v = g_y[(bt+rr)*256 + cc];
        float h = tf32_hi(v);
        smh[cc*68 + rr] = h; sml[cc*68 + rr] = v - h;
    }
    __syncthreads();
    const int lane = tid & 31, wrp = tid >> 5;
    const int g = lane >> 2, tig = lane & 3;
    const int mg = wrp >> 2, ng = wrp & 3;

    for (int np = 0; np < 4; np++) {
        const int ncol = np*256 + ng*64;
        float c[2][8][4];
        #pragma unroll
        for (int mm = 0; mm < 2; mm++)
            #pragma unroll
            for (int nt = 0; nt < 8; nt++)
                #pragma unroll
                for (int k = 0; k < 4; k++) c[mm][nt][k] = 0.f;
        for (int k8 = 0; k8 < 256; k8 += 8) {
            unsigned ah[2][4], al[2][4];
            #pragma unroll
            for (int mm = 0; mm < 2; mm++) {
                const int mb = mg*32 + mm*16 + g;
                const int a0 = (k8+tig)*68 + mb;
                const int a1 = (k8+tig+4)*68 + mb;
                ah[mm][0] = __float_as_uint(smh[a0]);
                ah[mm][1] = __float_as_uint(smh[a0+8]);
                ah[mm][2] = __float_as_uint(smh[a1]);
                ah[mm][3] = __float_as_uint(smh[a1+8]);
                al[mm][0] = __float_as_uint(sml[a0]);
                al[mm][1] = __float_as_uint(sml[a0+8]);
                al[mm][2] = __float_as_uint(sml[a1]);
                al[mm][3] = __float_as_uint(sml[a1+8]);
            }
            #pragma unroll
            for (int nt = 0; nt < 8; nt++) {
                const int col = ncol + nt*8 + g;
                const int kb = (k8+tig)*1024 + col;
                unsigned bh[2], bl[2];
                bh[0] = __float_as_uint(__ldg(&g_owhi[kb]));
                bh[1] = __float_as_uint(__ldg(&g_owhi[kb + 4*1024]));
                bl[0] = __float_as_uint(__ldg(&g_owlo[kb]));
                bl[1] = __float_as_uint(__ldg(&g_owlo[kb + 4*1024]));
                #pragma unroll
                for (int mm = 0; mm < 2; mm++) {
                    mma_tf32(c[mm][nt], ah[mm], bh);
                    mma_tf32(c[mm][nt], ah[mm], bl);
                    mma_tf32(c[mm][nt], al[mm], bh);
                }
            }
        }
        #pragma unroll
        for (int mm = 0; mm < 2; mm++)
            #pragma unroll
            for (int h = 0; h < 2; h++) {
                const int row = mg*32 + mm*16 + h*8 + g;
                float* orow = out + (bt+row)*NCLS;
                #pragma unroll
                for (int nt = 0; nt < 8; nt++) {
                    const int col = ncol + nt*8 + tig*2;
                    if (col < NCLS)
                        orow[col]   = c[mm][nt][h*2]   + __ldg(&ob[col]);
                    if (col+1 < NCLS)
                        orow[col+1] = c[mm][nt][h*2+1] + __ldg(&ob[col+1]);
                }
            }
    }
}

// ---------------- launch ----------------
extern "C" void kernel_launch(void* const* d_in, const int* in_sizes, int n_in,
                              void* d_out, int out_size) {
    const float* x   = (const float*)d_in[0];
    const float* c1w = (const float*)d_in[1];
    const float* c1b = (const float*)d_in[2];
    const float* c2w = (const float*)d_in[3];
    const float* c2b = (const float*)d_in[4];
    const float* c3w = (const float*)d_in[5];
    const float* c3b = (const float*)d_in[6];
    const float* fcw = (const float*)d_in[7];
    const float* fcb = (const float*)d_in[8];
    const float* gw  = (const float*)d_in[9];
    const float* gb  = (const float*)d_in[10];
    const float* ew1 = (const float*)d_in[11];
    const float* eb1 = (const float*)d_in[12];
    const float* ew2 = (const float*)d_in[13];
    const float* eb2 = (const float*)d_in[14];
    const float* lng = (const float*)d_in[15];
    const float* lnb = (const float*)d_in[16];
    const float* ow  = (const float*)d_in[17];
    const float* ob  = (const float*)d_in[18];
    float* out = (float*)d_out;

    cudaFuncSetAttribute(k_conv2t, cudaFuncAttributeMaxDynamicSharedMemorySize, C2_SMEM);
    cudaFuncSetAttribute(k_conv3t, cudaFuncAttributeMaxDynamicSharedMemorySize, C3_SMEM);
    cudaFuncSetAttribute(k_e1m, cudaFuncAttributeMaxDynamicSharedMemorySize, GE_SMEM);
    cudaFuncSetAttribute(k_e2m, cudaFuncAttributeMaxDynamicSharedMemorySize, GE_SMEM);
    cudaFuncSetAttribute(k_fcm, cudaFuncAttributeMaxDynamicSharedMemorySize, GE_SMEM);
    cudaFuncSetAttribute(k_outm, cudaFuncAttributeMaxDynamicSharedMemorySize, GE_SMEM);

    k_zero<<<1, 32>>>();
    k_wtrans<<<288, 256>>>(c2w, c3w);
    k_wprep<<<2048, 256>>>(ew1, ew2);
    k_wprep2<<<2048, 256>>>(fcw, ow);
    k_conv1<<<BATCH/2, 512>>>(x, c1w, c1b);
    k_conv2t<<<BATCH, 256, C2_SMEM>>>(c2b);
    k_conv3t<<<BATCH/2, 256, C3_SMEM>>>(c3b);
    k_fcm<<<BATCH/64, 256, GE_SMEM>>>(fcb);
    k_gate<<<BATCH/16, 256>>>(gw, gb);
    k_scan<<<1, 32>>>(out, out_size);
    k_scatter<<<BATCH*2/256, 256>>>();
    dim3 ge(128, 16);
    k_e1m<<<ge, 256, GE_SMEM>>>(eb1);
    k_e2m<<<ge, 256, GE_SMEM>>>(eb2);
    k_ln<<<BATCH, 256>>>(lng, lnb);
    k_outm<<<BATCH/64, 256, GE_SMEM>>>(ob, out);
}

// round 12
// speedup vs baseline: 1.0234x; 1.0234x over previous
#include <cuda_runtime.h>
#include <math.h>

#define BATCH 4096
#define NCLS  1000

// ---------------- scratch (device globals; no dynamic allocation) ----------------
__device__ float g_h1[BATCH*32*16*16];   // conv1 pooled out  [B,32,16,16]
__device__ float g_h2[BATCH*64*8*8];     // conv2 pooled out  [B,64,8,8]
__device__ float g_h3[BATCH*2048];       // conv3 pooled flat [B,2048]
__device__ float g_feat[BATCH*256];      // fc out            [B,256]
__device__ float g_y[BATCH*256];         // layernorm out     [B,256]
__device__ int   g_tidx[BATCH*2];        // top2 expert idx
__device__ float g_tg[BATCH*2];          // top2 gate weights
__device__ float g_gatesum[16];
__device__ int   g_counts[16];
__device__ int   g_offsets[16];
__device__ int   g_cursor[16];
__device__ int   g_list_b[BATCH*2];      // token id per grouped slot
__device__ float g_list_g[BATCH*2];      // gate weight per grouped slot
__device__ int   g_slotpos[BATCH*2];     // (b,k) -> grouped slot
__device__ float g_h1e[BATCH*2*1024];    // expert hidden per slot
__device__ float g_eo[BATCH*2*256];      // gate-scaled expert out per slot
// conv weights in MMA-fragment-packed layout:
// conv2: [(cc*9+t)*2 + ocg][m][lane][4]  (cc=ci/8, ocg=oc/32)
// conv3: [(cc*9+t)*4 + ocg][m][lane][4]
__device__ float g_p2hi[18432];
__device__ float g_p2lo[18432];
__device__ float g_p3hi[73728];
__device__ float g_p3lo[73728];
// expert weights split hi/lo (layout already [e][k][n])
__device__ float g_e1hi[16*262144];
__device__ float g_e1lo[16*262144];
__device__ float g_e2hi[16*262144];
__device__ float g_e2lo[16*262144];

// ---------------- tf32 helpers ----------------
__device__ __forceinline__ float tf32_hi(float x) {
    return __uint_as_float(__float_as_uint(x) & 0xFFFFE000u);
}

__device__ __forceinline__ void mma_tf32(float* c, const unsigned* a, const unsigned* b) {
    asm volatile(
        "mma.sync.aligned.m16n8k8.row.col.f32.tf32.tf32.f32 "
        "{%0,%1,%2,%3}, {%4,%5,%6,%7}, {%8,%9}, {%0,%1,%2,%3};"
        : "+f"(c[0]), "+f"(c[1]), "+f"(c[2]), "+f"(c[3])
        : "r"(a[0]), "r"(a[1]), "r"(a[2]), "r"(a[3]), "r"(b[0]), "r"(b[1]));
}

// ---------------- init ----------------
__global__ void k_zero() {
    int t = threadIdx.x;
    if (t < 16) { g_gatesum[t] = 0.f; g_counts[t] = 0; }
}

// ---------------- weight transpose: OIHW -> packed MMA fragments, hi/lo split ----------------
__global__ void k_wtrans(const float* __restrict__ c2w, const float* __restrict__ c3w) {
    int idx = blockIdx.x*256 + threadIdx.x;
    if (idx < 18432) {          // conv2: [64 oc][32 ci][9 t]
        int oc = idx / 288, rem = idx % 288;
        int ci = rem / 9, t = rem % 9;
        float v = c2w[idx];
        float hi = tf32_hi(v);
        int cc = ci >> 3, k = ci & 7;
        int ocg = oc >> 5, om = oc & 31;
        int m = om >> 4, r = om & 15;
        int g = r & 7, halfrow = r >> 3;
        int tig = k & 3, halfcol = k >> 2;
        int j = halfcol*2 + halfrow;
        int lane = g*4 + tig;
        int d = (((cc*9 + t)*2 + ocg)*2 + m)*128 + lane*4 + j;
        g_p2hi[d] = hi; g_p2lo[d] = v - hi;
    }
    if (idx < 73728) {          // conv3: [128 oc][64 ci][9 t]
        int oc = idx / 576, rem = idx % 576;
        int ci = rem / 9, t = rem % 9;
        float v = c3w[idx];
        float hi = tf32_hi(v);
        int cc = ci >> 3, k = ci & 7;
        int ocg = oc >> 5, om = oc & 31;
        int m = om >> 4, r = om & 15;
        int g = r & 7, halfrow = r >> 3;
        int tig = k & 3, halfcol = k >> 2;
        int j = halfcol*2 + halfrow;
        int lane = g*4 + tig;
        int d = (((cc*9 + t)*4 + ocg)*2 + m)*128 + lane*4 + j;
        g_p3hi[d] = hi; g_p3lo[d] = v - hi;
    }
}

// ---------------- expert weight hi/lo split ----------------
__global__ void k_wprep(const float* __restrict__ w1, const float* __restrict__ w2) {
    for (int i = blockIdx.x*256 + threadIdx.x; i < 16*262144; i += gridDim.x*256) {
        float v = w1[i]; float h = tf32_hi(v);
        g_e1hi[i] = h; g_e1lo[i] = v - h;
        v = w2[i]; h = tf32_hi(v);
        g_e2hi[i] = h; g_e2lo[i] = v - h;
    }
}

// ---------------- conv1: [B,3,32,32] -> pool -> relu -> [B,32,16,16] (2 img/block, fp32) ----------------
__global__ void __launch_bounds__(512) k_conv1(const float* __restrict__ x,
                                               const float* __restrict__ w,
                                               const float* __restrict__ bias) {
    __shared__ float xs[2*3*34*34];
    __shared__ float ws[27*36];
    __shared__ float bs[32];
    const int b0 = blockIdx.x*2, tid = threadIdx.x;
    for (int i = tid; i < 2*3468; i += 512) xs[i] = 0.f;
    if (tid < 32) bs[tid] = bias[tid];
    __syncthreads();
    for (int i = tid; i < 2*3072; i += 512) {
        int img = i / 3072, rem = i % 3072;
        int ci = rem >> 10, r2 = rem & 1023;
        xs[img*3468 + ci*1156 + ((r2>>5)+1)*34 + (r2&31) + 1] = x[(b0+img)*3072 + rem];
    }
    for (int i = tid; i < 864; i += 512)
        ws[(i%27)*36 + (i/27)] = w[i];
    __syncthreads();

    const int img = tid >> 8, t = tid & 255;
    const int py = t >> 4, px = t & 15;
    const float* xsI = xs + img*3468;
    float* outp = g_h1 + (b0+img)*8192;
    for (int cb = 0; cb < 32; cb += 8) {
        float acc[8][4];
        #pragma unroll
        for (int j = 0; j < 8; j++) { acc[j][0]=acc[j][1]=acc[j][2]=acc[j][3]=0.f; }
        #pragma unroll
        for (int ci = 0; ci < 3; ci++) {
            #pragma unroll
            for (int ky = 0; ky < 3; ky++) {
                #pragma unroll
                for (int kx = 0; kx < 3; kx++) {
                    const int kk = ci*9 + ky*3 + kx;
                    float wv[8];
                    *(float4*)&wv[0] = *(const float4*)&ws[kk*36 + cb];
                    *(float4*)&wv[4] = *(const float4*)&ws[kk*36 + cb + 4];
                    float iv[4];
                    #pragma unroll
                    for (int dy = 0; dy < 2; dy++)
                        #pragma unroll
                        for (int dx = 0; dx < 2; dx++)
                            iv[dy*2+dx] = xsI[ci*1156 + (2*py+dy+ky)*34 + (2*px+dx+kx)];
                    #pragma unroll
                    for (int j = 0; j < 8; j++)
                        #pragma unroll
                        for (int p = 0; p < 4; p++)
                            acc[j][p] += wv[j]*iv[p];
                }
            }
        }
        #pragma unroll
        for (int j = 0; j < 8; j++) {
            float m = fmaxf(fmaxf(acc[j][0],acc[j][1]), fmaxf(acc[j][2],acc[j][3]));
            outp[(cb+j)*256 + t] = fmaxf(m + bs[cb+j], 0.f);
        }
    }
}

// ---------------- conv2: tensor-core 3xTF32 tap-GEMM, packed A + float2 B ----------------
// 1 img/block, 256 thr = 8 warps = 2 ocg(32 oc) x 4 posg(4 rows y).
#define C2_SMEM (10368*8)
__global__ void __launch_bounds__(256) k_conv2t(const float* __restrict__ bias) {
    extern __shared__ float2 in2[];   // (hi, lo) interleaved, 32*18*18 padded
    const int b = blockIdx.x, tid = threadIdx.x;
    for (int i = tid; i < 10368; i += 256) in2[i] = make_float2(0.f, 0.f);
    __syncthreads();
    for (int i = tid; i < 8192; i += 256) {
        int ci = i >> 8, r2 = i & 255;
        float v = g_h1[b*8192 + i];
        float hi = tf32_hi(v);
        int d = ci*324 + ((r2>>4)+1)*18 + (r2&15) + 1;
        in2[d] = make_float2(hi, v - hi);
    }
    __syncthreads();

    const int lane = tid & 31, wrp = tid >> 5;
    const int g = lane >> 2, tig = lane & 3;
    const int ocg = wrp >> 2, posg = wrp & 3;
    const int y0 = posg*4;
    const int ocm = ocg*32;

    float c[2][8][4];
    #pragma unroll
    for (int m = 0; m < 2; m++)
        #pragma unroll
        for (int nt = 0; nt < 8; nt++)
            #pragma unroll
            for (int k = 0; k < 4; k++) c[m][nt][k] = 0.f;

    const int blane = tig*324 + g;

    for (int cc = 0; cc < 4; cc++) {
        const int c8 = cc*8;
        #pragma unroll
        for (int t = 0; t < 9; t++) {
            const int ky = t/3, kx = t%3;
            const int pb = (((cc*9 + t)*2 + ocg)*2)*128 + lane*4;
            unsigned ah[2][4], al[2][4];
            #pragma unroll
            for (int m = 0; m < 2; m++) {
                float4 fh = *(const float4*)&g_p2hi[pb + m*128];
                float4 fl = *(const float4*)&g_p2lo[pb + m*128];
                ah[m][0] = __float_as_uint(fh.x); ah[m][1] = __float_as_uint(fh.y);
                ah[m][2] = __float_as_uint(fh.z); ah[m][3] = __float_as_uint(fh.w);
                al[m][0] = __float_as_uint(fl.x); al[m][1] = __float_as_uint(fl.y);
                al[m][2] = __float_as_uint(fl.z); al[m][3] = __float_as_uint(fl.w);
            }
            const int bstep = c8*324 + blane + kx;
            #pragma unroll
            for (int nt = 0; nt < 8; nt++) {
                const int ry = nt >> 1, xh = nt & 1;
                const int ba = bstep + (y0+ry+ky)*18 + xh*8;
                float2 p0 = in2[ba];
                float2 p1 = in2[ba + 4*324];
                unsigned bh[2], bl[2];
                bh[0] = __float_as_uint(p0.x); bl[0] = __float_as_uint(p0.y);
                bh[1] = __float_as_uint(p1.x); bl[1] = __float_as_uint(p1.y);
                #pragma unroll
                for (int m = 0; m < 2; m++) {
                    mma_tf32(c[m][nt], ah[m], bh);
                    mma_tf32(c[m][nt], ah[m], bl);
                    mma_tf32(c[m][nt], al[m], bh);
                }
            }
        }
    }

    float* outp = g_h2 + b*4096;
    #pragma unroll
    for (int m = 0; m < 2; m++) {
        #pragma unroll
        for (int h = 0; h < 2; h++) {
            const int oc = ocm + m*16 + h*8 + g;
            const float bv = __ldg(&bias[oc]);
            const int k0 = h*2;
            #pragma unroll
            for (int pr = 0; pr < 2; pr++) {
                #pragma unroll
                for (int xh = 0; xh < 2; xh++) {
                    const int nta = (2*pr)*2 + xh, ntb = nta + 2;
                    float v = fmaxf(fmaxf(c[m][nta][k0], c[m][nta][k0+1]),
                                    fmaxf(c[m][ntb][k0], c[m][ntb][k0+1]));
                    outp[oc*64 + (posg*2+pr)*8 + xh*4 + tig] = fmaxf(v + bv, 0.f);
                }
            }
        }
    }
}

// ---------------- conv3: tensor-core 3xTF32 tap-GEMM, packed A + float2 B ----------------
// 2 img/block, 256 thr = 8 warps = 2 img x 4 ocg(32 oc); each warp: all 64 pos.
#define C3_SMEM (2*6400*8)
__global__ void __launch_bounds__(256) k_conv3t(const float* __restrict__ bias) {
    extern __shared__ float2 in2[];   // [img][6400] (hi,lo)
    const int b0 = blockIdx.x*2, tid = threadIdx.x;
    for (int i = tid; i < 12800; i += 256) in2[i] = make_float2(0.f, 0.f);
    __syncthreads();
    for (int i = tid; i < 8192; i += 256) {
        int img = i >> 12, rem = i & 4095;
        int ci = rem >> 6, r2 = rem & 63;
        float v = g_h2[(b0+img)*4096 + rem];
        float hi = tf32_hi(v);
        int d = img*6400 + ci*100 + ((r2>>3)+1)*10 + (r2&7) + 1;
        in2[d] = make_float2(hi, v - hi);
    }
    __syncthreads();

    const int lane = tid & 31, wrp = tid >> 5;
    const int g = lane >> 2, tig = lane & 3;
    const int img = wrp >> 2, ocg = wrp & 3;
    const int ocm = ocg*32;
    const float2* inI = in2 + img*6400;

    float c[2][8][4];
    #pragma unroll
    for (int m = 0; m < 2; m++)
        #pragma unroll
        for (int nt = 0; nt < 8; nt++)
            #pragma unroll
            for (int k = 0; k < 4; k++) c[m][nt][k] = 0.f;

    const int blane = tig*100 + g;

    for (int cc = 0; cc < 8; cc++) {
        const int c8 = cc*8;
        #pragma unroll
        for (int t = 0; t < 9; t++) {
            const int ky = t/3, kx = t%3;
            const int pb = (((cc*9 + t)*4 + ocg)*2)*128 + lane*4;
            unsigned ah[2][4], al[2][4];
            #pragma unroll
            for (int m = 0; m < 2; m++) {
                float4 fh = *(const float4*)&g_p3hi[pb + m*128];
                float4 fl = *(const float4*)&g_p3lo[pb + m*128];
                ah[m][0] = __float_as_uint(fh.x); ah[m][1] = __float_as_uint(fh.y);
                ah[m][2] = __float_as_uint(fh.z); ah[m][3] = __float_as_uint(fh.w);
                al[m][0] = __float_as_uint(fl.x); al[m][1] = __float_as_uint(fl.y);
                al[m][2] = __float_as_uint(fl.z); al[m][3] = __float_as_uint(fl.w);
            }
            const int bstep = c8*100 + blane + kx;
            #pragma unroll
            for (int nt = 0; nt < 8; nt++) {
                const int ba = bstep + (nt+ky)*10;
                float2 p0 = inI[ba];
                float2 p1 = inI[ba + 4*100];
                unsigned bh[2], bl[2];
                bh[0] = __float_as_uint(p0.x); bl[0] = __float_as_uint(p0.y);
                bh[1] = __float_as_uint(p1.x); bl[1] = __float_as_uint(p1.y);
                #pragma unroll
                for (int m = 0; m < 2; m++) {
                    mma_tf32(c[m][nt], ah[m], bh);
                    mma_tf32(c[m][nt], ah[m], bl);
                    mma_tf32(c[m][nt], al[m], bh);
                }
            }
        }
    }

    float* outp = g_h3 + (b0+img)*2048;
    #pragma unroll
    for (int m = 0; m < 2; m++) {
        #pragma unroll
        for (int h = 0; h < 2; h++) {
            const int oc = ocm + m*16 + h*8 + g;
            const float bv = __ldg(&bias[oc]);
            const int k0 = h*2;
            #pragma unroll
            for (int py = 0; py < 4; py++) {
                float v = fmaxf(fmaxf(c[m][2*py][k0], c[m][2*py][k0+1]),
                                fmaxf(c[m][2*py+1][k0], c[m][2*py+1][k0+1]));
                outp[oc*16 + py*4 + tig] = fmaxf(v + bv, 0.f);
            }
        }
    }
}

// ---------------- fc: [B,2048] @ [2048,256] (FFMA, R10 version) ----------------
__global__ void __launch_bounds__(256) k_fc(const float* __restrict__ fcw,
                                            const float* __restrict__ fcb) {
    __shared__ float hs[32*256];
    const int bt = blockIdx.x*32, tid = threadIdx.x;
    const int tx = tid & 63, ty = tid >> 6;
    float acc[8][4];
    #pragma unroll
    for (int i = 0; i < 8; i++) { acc[i][0]=acc[i][1]=acc[i][2]=acc[i][3]=0.f; }
    for (int kc = 0; kc < 8; kc++) {
        __syncthreads();
        for (int i = tid; i < 8192; i += 256) {
            int rr = i >> 8, c = i & 255;
            hs[i] = g_h3[(bt+rr)*2048 + kc*256 + c];
        }
        __syncthreads();
        for (int d = 0; d < 256; d++) {
            float4 wv = *(const float4*)&fcw[(kc*256+d)*256 + tx*4];
            #pragma unroll
            for (int i = 0; i < 8; i++) {
                float f = hs[(ty*8+i)*256 + d];
                acc[i][0] += f*wv.x; acc[i][1] += f*wv.y;
                acc[i][2] += f*wv.z; acc[i][3] += f*wv.w;
            }
        }
    }
    float4 bb = *(const float4*)&fcb[tx*4];
    #pragma unroll
    for (int i = 0; i < 8; i++) {
        float* o = &g_feat[(bt+ty*8+i)*256 + tx*4];
        o[0] = acc[i][0]+bb.x; o[1] = acc[i][1]+bb.y;
        o[2] = acc[i][2]+bb.z; o[3] = acc[i][3]+bb.w;
    }
}

// ---------------- gate: logits, top-2, softmax, counts ----------------
__global__ void __launch_bounds__(256) k_gate(const float* __restrict__ gw,
                                              const float* __restrict__ gb) {
    __shared__ float fs[16*256];
    __shared__ float ls[16*17];
    const int b0 = blockIdx.x*16, tid = threadIdx.x;
    for (int i = tid; i < 4096; i += 256) fs[i] = g_feat[b0*256 + i];
    __syncthreads();
    const int t = tid >> 4, e = tid & 15;
    float acc = gb[e];
    for (int d = 0; d < 256; d++) acc += fs[t*256+d]*__ldg(&gw[d*16+e]);
    ls[t*17+e] = acc;
    __syncthreads();
    if (e == 0) {
        const float* l = &ls[t*17];
        int i1 = 0; float v1 = l[0];
        #pragma unroll
        for (int i = 1; i < 16; i++) if (l[i] > v1) { v1 = l[i]; i1 = i; }
        int i2 = -1; float v2 = -1e30f;
        #pragma unroll
        for (int i = 0; i < 16; i++) if (i != i1 && l[i] > v2) { v2 = l[i]; i2 = i; }
        float e2 = expf(v2 - v1);
        float inv = 1.0f/(1.0f + e2);
        float g1 = inv, g2 = e2*inv;
        int b = b0 + t;
        g_tidx[b*2] = i1;  g_tidx[b*2+1] = i2;
        g_tg[b*2]   = g1;  g_tg[b*2+1]   = g2;
        atomicAdd(&g_gatesum[i1], g1);
        atomicAdd(&g_gatesum[i2], g2);
        atomicAdd(&g_counts[i1], 1);
        atomicAdd(&g_counts[i2], 1);
    }
}

// ---------------- scan offsets + lb_loss ----------------
__global__ void k_scan(float* d_out, int out_size) {
    if (threadIdx.x == 0) {
        int off = 0;
        for (int e = 0; e < 16; e++) {
            g_offsets[e] = off; g_cursor[e] = off; off += g_counts[e];
        }
        float loss = 0.f;
        for (int e = 0; e < 16; e++) {
            float di = g_gatesum[e] / (float)BATCH;
            loss += di * logf(di + 1e-8f);
        }
        if (out_size > BATCH*NCLS) d_out[BATCH*NCLS] = loss;
    }
}

// ---------------- scatter tokens into expert-grouped lists ----------------
__global__ void k_scatter() {
    int s = blockIdx.x*256 + threadIdx.x;
    int e = g_tidx[s];
    int pos = atomicAdd(&g_cursor[e], 1);
    g_list_b[pos] = s >> 1;
    g_list_g[pos] = g_tg[s];
    g_slotpos[s] = pos;
}

// ---------------- expert pass A (MMA): h1 = relu(feat @ w1 + b1) ----------------
#define GE_SMEM (2*256*68*4)
__global__ void __launch_bounds__(256) k_e1m(const float* __restrict__ b1) {
    const int e = blockIdx.y;
    const int cnt = g_counts[e];
    const int ts = blockIdx.x*64;
    if (ts >= cnt) return;
    const int off = g_offsets[e];
    const int rows = min(64, cnt - ts);
    extern __shared__ float sm[];
    float* smh = sm;
    float* sml = sm + 256*68;
    const int tid = threadIdx.x;
    for (int i = tid; i < 64*256; i += 256) {
        int rr = i >> 8, cc = i & 255;
        float v = (rr < rows) ? g_feat[g_list_b[off+ts+rr]*256 + cc] : 0.f;
        float h = tf32_hi(v);
        smh[cc*68 + rr] = h; sml[cc*68 + rr] = v - h;
    }
    __syncthreads();
    const int lane = tid & 31, wrp = tid >> 5;
    const int g = lane >> 2, tig = lane & 3;
    const int mg = wrp >> 2, ng = wrp & 3;
    const float* Whi = g_e1hi + e*262144;
    const float* Wlo = g_e1lo + e*262144;

    for (int np = 0; np < 4; np++) {
        const int ncol = np*256 + ng*64;
        float c[2][8][4];
        #pragma unroll
        for (int mm = 0; mm < 2; mm++)
            #pragma unroll
            for (int nt = 0; nt < 8; nt++)
                #pragma unroll
                for (int k = 0; k < 4; k++) c[mm][nt][k] = 0.f;
        for (int k8 = 0; k8 < 256; k8 += 8) {
            unsigned ah[2][4], al[2][4];
            #pragma unroll
            for (int mm = 0; mm < 2; mm++) {
                const int mb = mg*32 + mm*16 + g;
                const int a0 = (k8+tig)*68 + mb;
                const int a1 = (k8+tig+4)*68 + mb;
                ah[mm][0] = __float_as_uint(smh[a0]);
                ah[mm][1] = __float_as_uint(smh[a0+8]);
                ah[mm][2] = __float_as_uint(smh[a1]);
                ah[mm][3] = __float_as_uint(smh[a1+8]);
                al[mm][0] = __float_as_uint(sml[a0]);
                al[mm][1] = __float_as_uint(sml[a0+8]);
                al[mm][2] = __float_as_uint(sml[a1]);
                al[mm][3] = __float_as_uint(sml[a1+8]);
            }
            #pragma unroll
            for (int nt = 0; nt < 8; nt++) {
                const int col = ncol + nt*8 + g;
                const int kb = (k8+tig)*1024 + col;
                unsigned bh[2], bl[2];
                bh[0] = __float_as_uint(__ldg(&Whi[kb]));
                bh[1] = __float_as_uint(__ldg(&Whi[kb + 4*1024]));
                bl[0] = __float_as_uint(__ldg(&Wlo[kb]));
                bl[1] = __float_as_uint(__ldg(&Wlo[kb + 4*1024]));
                #pragma unroll
                for (int mm = 0; mm < 2; mm++) {
                    mma_tf32(c[mm][nt], ah[mm], bh);
                    mma_tf32(c[mm][nt], ah[mm], bl);
                    mma_tf32(c[mm][nt], al[mm], bh);
                }
            }
        }
        #pragma unroll
        for (int mm = 0; mm < 2; mm++)
            #pragma unroll
            for (int h = 0; h < 2; h++) {
                const int row = mg*32 + mm*16 + h*8 + g;
                if (row < rows) {
                    const int slot = off + ts + row;
                    #pragma unroll
                    for (int nt = 0; nt < 8; nt++) {
                        const int col = ncol + nt*8 + tig*2;
                        float v0 = c[mm][nt][h*2]   + __ldg(&b1[e*1024+col]);
                        float v1 = c[mm][nt][h*2+1] + __ldg(&b1[e*1024+col+1]);
                        g_h1e[slot*1024 + col]   = fmaxf(v0, 0.f);
                        g_h1e[slot*1024 + col+1] = fmaxf(v1, 0.f);
                    }
                }
            }
    }
}

// ---------------- expert pass B (MMA): eo = gate*(h1 @ w2 + b2) ----------------
__global__ void __launch_bounds__(256) k_e2m(const float* __restrict__ b2) {
    const int e = blockIdx.y;
    const int cnt = g_counts[e];
    const int ts = blockIdx.x*64;
    if (ts >= cnt) return;
    const int off = g_offsets[e];
    const int rows = min(64, cnt - ts);
    extern __shared__ float sm[];
    float* smh = sm;
    float* sml = sm + 256*68;
    const int tid = threadIdx.x;
    const int lane = tid & 31, wrp = tid >> 5;
    const int g = lane >> 2, tig = lane & 3;
    const int mg = wrp >> 2, ng = wrp & 3;
    const float* Whi = g_e2hi + e*262144;
    const float* Wlo = g_e2lo + e*262144;

    float c[2][8][4];
    #pragma unroll
    for (int mm = 0; mm < 2; mm++)
        #pragma unroll
        for (int nt = 0; nt < 8; nt++)
            #pragma unroll
            for (int k = 0; k < 4; k++) c[mm][nt][k] = 0.f;

    for (int st = 0; st < 4; st++) {
        __syncthreads();
        for (int i = tid; i < 64*256; i += 256) {
            int rr = i >> 8, cc = i & 255;
            float v = (rr < rows) ? g_h1e[(off+ts+rr)*1024 + st*256 + cc] : 0.f;
            float h = tf32_hi(v);
            smh[cc*68 + rr] = h; sml[cc*68 + rr] = v - h;
        }
        __syncthreads();
        for (int k8 = 0; k8 < 256; k8 += 8) {
            unsigned ah[2][4], al[2][4];
            #pragma unroll
            for (int mm = 0; mm < 2; mm++) {
                const int mb = mg*32 + mm*16 + g;
                const int a0 = (k8+tig)*68 + mb;
                const int a1 = (k8+tig+4)*68 + mb;
                ah[mm][0] = __float_as_uint(smh[a0]);
                ah[mm][1] = __float_as_uint(smh[a0+8]);
                ah[mm][2] = __float_as_uint(smh[a1]);
                ah[mm][3] = __float_as_uint(smh[a1+8]);
                al[mm][0] = __float_as_uint(sml[a0]);
                al[mm][1] = __float_as_uint(sml[a0+8]);
                al[mm][2] = __float_as_uint(sml[a1]);
                al[mm][3] = __float_as_uint(sml[a1+8]);
            }
            #pragma unroll
            for (int nt = 0; nt < 8; nt++) {
                const int col = ng*64 + nt*8 + g;
                const int kb = (st*256 + k8 + tig)*256 + col;
                unsigned bh[2], bl[2];
                bh[0] = __float_as_uint(__ldg(&Whi[kb]));
                bh[1] = __float_as_uint(__ldg(&Whi[kb + 4*256]));
                bl[0] = __float_as_uint(__ldg(&Wlo[kb]));
                bl[1] = __float_as_uint(__ldg(&Wlo[kb + 4*256]));
                #pragma unroll
                for (int mm = 0; mm < 2; mm++) {
                    mma_tf32(c[mm][nt], ah[mm], bh);
                    mma_tf32(c[mm][nt], ah[mm], bl);
                    mma_tf32(c[mm][nt], al[mm], bh);
                }
            }
        }
    }
    #pragma unroll
    for (int mm = 0; mm < 2; mm++)
        #pragma unroll
        for (int h = 0; h < 2; h++) {
            const int row = mg*32 + mm*16 + h*8 + g;
            if (row < rows) {
                const int slot = off + ts + row;
                const float gt = g_list_g[slot];
                #pragma unroll
                for (int nt = 0; nt < 8; nt++) {
                    const int col = ng*64 + nt*8 + tig*2;
                    float v0 = c[mm][nt][h*2]   + __ldg(&b2[e*256+col]);
                    float v1 = c[mm][nt][h*2+1] + __ldg(&b2[e*256+col+1]);
                    g_eo[slot*256 + col]   = gt*v0;
                    g_eo[slot*256 + col+1] = gt*v1;
                }
            }
        }
}

// ---------------- combine + residual + LayerNorm ----------------
__global__ void __launch_bounds__(256) k_ln(const float* __restrict__ lng,
                                            const float* __restrict__ lnb) {
    const int b = blockIdx.x, tid = threadIdx.x;
    const int p0 = g_slotpos[b*2], p1 = g_slotpos[b*2+1];
    float y = g_eo[p0*256+tid] + g_eo[p1*256+tid] + g_feat[b*256+tid];
    __shared__ float red[16];
    __shared__ float mu_s, rstd_s;
    float s = y, s2 = y*y;
    #pragma unroll
    for (int o = 16; o > 0; o >>= 1) {
        s  += __shfl_xor_sync(0xffffffffu, s,  o);
        s2 += __shfl_xor_sync(0xffffffffu, s2, o);
    }
    if ((tid & 31) == 0) { red[tid>>5] = s; red[8 + (tid>>5)] = s2; }
    __syncthreads();
    if (tid == 0) {
        float S = 0.f, S2 = 0.f;
        #pragma unroll
        for (int i = 0; i < 8; i++) { S += red[i]; S2 += red[8+i]; }
        float mu = S/256.f;
        mu_s = mu;
        rstd_s = rsqrtf(S2/256.f - mu*mu + 1e-5f);
    }
    __syncthreads();
    g_y[b*256+tid] = (y - mu_s)*rstd_s*lng[tid] + lnb[tid];
}

// ---------------- output projection: [B,256] @ [256,1000] (FFMA, R10 version) ----------------
__global__ void __launch_bounds__(256) k_out(const float* __restrict__ ow,
                                             const float* __restrict__ ob,
                                             float* __restrict__ out) {
    __shared__ float ys[32*256];
    const int bt = blockIdx.y*32, cb = blockIdx.x*256, tid = threadIdx.x;
    for (int i = tid; i < 8192; i += 256) ys[i] = g_y[bt*256 + i];
    __syncthreads();
    const int tx = tid & 63, ty = tid >> 6;
    const int c = cb + tx*4;
    bool v0 = c < NCLS, v1 = c+1 < NCLS, v2 = c+2 < NCLS, v3 = c+3 < NCLS;
    float acc[8][4];
    #pragma unroll
    for (int i = 0; i < 8; i++) { acc[i][0]=acc[i][1]=acc[i][2]=acc[i][3]=0.f; }
    for (int d = 0; d < 256; d++) {
        const float* wr = ow + d*NCLS;
        float w0 = v0 ? wr[c]   : 0.f;
        float w1 = v1 ? wr[c+1] : 0.f;
        float w2 = v2 ? wr[c+2] : 0.f;
        float w3 = v3 ? wr[c+3] : 0.f;
        #pragma unroll
        for (int i = 0; i < 8; i++) {
            float f = ys[(ty*8+i)*256 + d];
            acc[i][0] += f*w0; acc[i][1] += f*w1;
            acc[i][2] += f*w2; acc[i][3] += f*w3;
        }
    }
    float b0 = v0 ? ob[c] : 0.f, b1 = v1 ? ob[c+1] : 0.f;
    float b2 = v2 ? ob[c+2] : 0.f, b3 = v3 ? ob[c+3] : 0.f;
    #pragma unroll
    for (int i = 0; i < 8; i++) {
        float* o = out + (bt+ty*8+i)*NCLS;
        if (v0) o[c]   = acc[i][0] + b0;
        if (v1) o[c+1] = acc[i][1] + b1;
        if (v2) o[c+2] = acc[i][2] + b2;
        if (v3) o[c+3] = acc[i][3] + b3;
    }
}

// ---------------- launch ----------------
extern "C" void kernel_launch(void* const* d_in, const int* in_sizes, int n_in,
                              void* d_out, int out_size) {
    const float* x   = (const float*)d_in[0];
    const float* c1w = (const float*)d_in[1];
    const float* c1b = (const float*)d_in[2];
    const float* c2w = (const float*)d_in[3];
    const float* c2b = (const float*)d_in[4];
    const float* c3w = (const float*)d_in[5];
    const float* c3b = (const float*)d_in[6];
    const float* fcw = (const float*)d_in[7];
    const float* fcb = (const float*)d_in[8];
    const float* gw  = (const float*)d_in[9];
    const float* gb  = (const float*)d_in[10];
    const float* ew1 = (const float*)d_in[11];
    const float* eb1 = (const float*)d_in[12];
    const float* ew2 = (const float*)d_in[13];
    const float* eb2 = (const float*)d_in[14];
    const float* lng = (const float*)d_in[15];
    const float* lnb = (const float*)d_in[16];
    const float* ow  = (const float*)d_in[17];
    const float* ob  = (const float*)d_in[18];
    float* out = (float*)d_out;

    cudaFuncSetAttribute(k_conv2t, cudaFuncAttributeMaxDynamicSharedMemorySize, C2_SMEM);
    cudaFuncSetAttribute(k_conv3t, cudaFuncAttributeMaxDynamicSharedMemorySize, C3_SMEM);
    cudaFuncSetAttribute(k_e1m, cudaFuncAttributeMaxDynamicSharedMemorySize, GE_SMEM);
    cudaFuncSetAttribute(k_e2m, cudaFuncAttributeMaxDynamicSharedMemorySize, GE_SMEM);

    k_zero<<<1, 32>>>();
    k_wtrans<<<288, 256>>>(c2w, c3w);
    k_wprep<<<2048, 256>>>(ew1, ew2);
    k_conv1<<<BATCH/2, 512>>>(x, c1w, c1b);
    k_conv2t<<<BATCH, 256, C2_SMEM>>>(c2b);
    k_conv3t<<<BATCH/2, 256, C3_SMEM>>>(c3b);
    k_fc<<<BATCH/32, 256>>>(fcw, fcb);
    k_gate<<<BATCH/16, 256>>>(gw, gb);
    k_scan<<<1, 32>>>(out, out_size);
    k_scatter<<<BATCH*2/256, 256>>>();
    dim3 ge(128, 16);
    k_e1m<<<ge, 256, GE_SMEM>>>(eb1);
    k_e2m<<<ge, 256, GE_SMEM>>>(eb2);
    k_ln<<<BATCH, 256>>>(lng, lnb);
    dim3 go(4, BATCH/32);
    k_out<<<go, 256>>>(ow, ob, out);
}

// round 13
// speedup vs baseline: 1.0564x; 1.0322x over previous
#include <cuda_runtime.h>
#include <math.h>

#define BATCH 4096
#define NCLS  1000

// ---------------- scratch (device globals; no dynamic allocation) ----------------
__device__ float g_h1[BATCH*32*16*16];   // conv1 pooled out  [B,32,16,16]
__device__ float g_h2[BATCH*64*8*8];     // conv2 pooled out  [B,64,8,8]
__device__ float g_h3[BATCH*2048];       // conv3 pooled flat [B,2048]
__device__ float g_feat[BATCH*256];      // fc out            [B,256]
__device__ float g_y[BATCH*256];         // layernorm out     [B,256]
__device__ int   g_tidx[BATCH*2];        // top2 expert idx
__device__ float g_tg[BATCH*2];          // top2 gate weights
__device__ float g_gatesum[16];
__device__ int   g_counts[16];
__device__ int   g_offsets[16];
__device__ int   g_cursor[16];
__device__ int   g_list_b[BATCH*2];      // token id per grouped slot
__device__ float g_list_g[BATCH*2];      // gate weight per grouped slot
__device__ int   g_slotpos[BATCH*2];     // (b,k) -> grouped slot
__device__ float g_h1e[BATCH*2*1024];    // expert hidden per slot
__device__ float g_eo[BATCH*2*256];      // gate-scaled expert out per slot
// conv weights transposed to [tap][ci][oc], split hi/lo tf32
__device__ float g_wt2hi[9*32*64];
__device__ float g_wt2lo[9*32*64];
__device__ float g_wt3hi[9*64*128];
__device__ float g_wt3lo[9*64*128];
// expert weights split hi/lo (layout already [e][k][n])
__device__ float g_e1hi[16*262144];
__device__ float g_e1lo[16*262144];
__device__ float g_e2hi[16*262144];
__device__ float g_e2lo[16*262144];

// ---------------- tf32 helpers ----------------
__device__ __forceinline__ float tf32_hi(float x) {
    return __uint_as_float(__float_as_uint(x) & 0xFFFFE000u);
}

__device__ __forceinline__ void mma_tf32(float* c, const unsigned* a, const unsigned* b) {
    asm volatile(
        "mma.sync.aligned.m16n8k8.row.col.f32.tf32.tf32.f32 "
        "{%0,%1,%2,%3}, {%4,%5,%6,%7}, {%8,%9}, {%0,%1,%2,%3};"
        : "+f"(c[0]), "+f"(c[1]), "+f"(c[2]), "+f"(c[3])
        : "r"(a[0]), "r"(a[1]), "r"(a[2]), "r"(a[3]), "r"(b[0]), "r"(b[1]));
}

// ---------------- init ----------------
__global__ void k_zero() {
    int t = threadIdx.x;
    if (t < 16) { g_gatesum[t] = 0.f; g_counts[t] = 0; }
}

// ---------------- weight transpose: OIHW -> [tap][ci][oc], hi/lo split ----------------
__global__ void k_wtrans(const float* __restrict__ c2w, const float* __restrict__ c3w) {
    int idx = blockIdx.x*256 + threadIdx.x;
    if (idx < 18432) {          // conv2: [64][32][9]
        int oc = idx / 288, rem = idx % 288;
        int ci = rem / 9, t = rem % 9;
        float v = c2w[idx];
        float hi = tf32_hi(v);
        int d = (t*32 + ci)*64 + oc;
        g_wt2hi[d] = hi; g_wt2lo[d] = v - hi;
    }
    if (idx < 73728) {          // conv3: [128][64][9]
        int oc = idx / 576, rem = idx % 576;
        int ci = rem / 9, t = rem % 9;
        float v = c3w[idx];
        float hi = tf32_hi(v);
        int d = (t*64 + ci)*128 + oc;
        g_wt3hi[d] = hi; g_wt3lo[d] = v - hi;
    }
}

// ---------------- expert weight hi/lo split ----------------
__global__ void k_wprep(const float* __restrict__ w1, const float* __restrict__ w2) {
    for (int i = blockIdx.x*256 + threadIdx.x; i < 16*262144; i += gridDim.x*256) {
        float v = w1[i]; float h = tf32_hi(v);
        g_e1hi[i] = h; g_e1lo[i] = v - h;
        v = w2[i]; h = tf32_hi(v);
        g_e2hi[i] = h; g_e2lo[i] = v - h;
    }
}

// ---------------- conv1: [B,3,32,32] -> pool -> relu -> [B,32,16,16] ----------------
// 2 img/block; reg-capped to 64 so 2 CTAs/SM (32 warps) fit.
__global__ void __launch_bounds__(512, 2) k_conv1(const float* __restrict__ x,
                                                  const float* __restrict__ w,
                                                  const float* __restrict__ bias) {
    __shared__ float xs[2*3*34*34];
    __shared__ float ws[27*36];
    __shared__ float bs[32];
    const int b0 = blockIdx.x*2, tid = threadIdx.x;
    for (int i = tid; i < 2*3468; i += 512) xs[i] = 0.f;
    if (tid < 32) bs[tid] = bias[tid];
    __syncthreads();
    for (int i = tid; i < 2*3072; i += 512) {
        int img = i / 3072, rem = i % 3072;
        int ci = rem >> 10, r2 = rem & 1023;
        xs[img*3468 + ci*1156 + ((r2>>5)+1)*34 + (r2&31) + 1] = x[(b0+img)*3072 + rem];
    }
    for (int i = tid; i < 864; i += 512)
        ws[(i%27)*36 + (i/27)] = w[i];
    __syncthreads();

    const int img = tid >> 8, t = tid & 255;
    const int py = t >> 4, px = t & 15;
    const float* xsI = xs + img*3468;
    float* outp = g_h1 + (b0+img)*8192;
    for (int cb = 0; cb < 32; cb += 8) {
        float acc[8][4];
        #pragma unroll
        for (int j = 0; j < 8; j++) { acc[j][0]=acc[j][1]=acc[j][2]=acc[j][3]=0.f; }
        #pragma unroll
        for (int ci = 0; ci < 3; ci++) {
            #pragma unroll
            for (int ky = 0; ky < 3; ky++) {
                #pragma unroll
                for (int kx = 0; kx < 3; kx++) {
                    const int kk = ci*9 + ky*3 + kx;
                    float wv[8];
                    *(float4*)&wv[0] = *(const float4*)&ws[kk*36 + cb];
                    *(float4*)&wv[4] = *(const float4*)&ws[kk*36 + cb + 4];
                    float iv[4];
                    #pragma unroll
                    for (int dy = 0; dy < 2; dy++)
                        #pragma unroll
                        for (int dx = 0; dx < 2; dx++)
                            iv[dy*2+dx] = xsI[ci*1156 + (2*py+dy+ky)*34 + (2*px+dx+kx)];
                    #pragma unroll
                    for (int j = 0; j < 8; j++)
                        #pragma unroll
                        for (int p = 0; p < 4; p++)
                            acc[j][p] += wv[j]*iv[p];
                }
            }
        }
        #pragma unroll
        for (int j = 0; j < 8; j++) {
            float m = fmaxf(fmaxf(acc[j][0],acc[j][1]), fmaxf(acc[j][2],acc[j][3]));
            outp[(cb+j)*256 + t] = fmaxf(m + bs[cb+j], 0.f);
        }
    }
}

// ---------------- conv2: tensor-core 3xTF32 tap-GEMM (R6/R10 version) ----------------
// 1 img/block, 256 thr = 8 warps = 2 ocg(32 oc) x 4 posg(4 rows y).
#define C2_SMEM (2*10368*4)
__global__ void __launch_bounds__(256) k_conv2t(const float* __restrict__ bias) {
    extern __shared__ float sm[];
    float* in_hi = sm;            // 32*18*18 padded
    float* in_lo = sm + 10368;
    const int b = blockIdx.x, tid = threadIdx.x;
    for (int i = tid; i < 10368; i += 256) { in_hi[i] = 0.f; in_lo[i] = 0.f; }
    __syncthreads();
    for (int i = tid; i < 8192; i += 256) {
        int ci = i >> 8, r2 = i & 255;
        float v = g_h1[b*8192 + i];
        float hi = tf32_hi(v);
        int d = ci*324 + ((r2>>4)+1)*18 + (r2&15) + 1;
        in_hi[d] = hi; in_lo[d] = v - hi;
    }
    __syncthreads();

    const int lane = tid & 31, wrp = tid >> 5;
    const int g = lane >> 2, tig = lane & 3;
    const int ocg = wrp >> 2, posg = wrp & 3;
    const int y0 = posg*4;
    const int ocm = ocg*32;

    float c[2][8][4];
    #pragma unroll
    for (int m = 0; m < 2; m++)
        #pragma unroll
        for (int nt = 0; nt < 8; nt++)
            #pragma unroll
            for (int k = 0; k < 4; k++) c[m][nt][k] = 0.f;

    const int blane = tig*324 + g;
    const int wlane = tig*64 + ocm + g;

    for (int c8 = 0; c8 < 32; c8 += 8) {
        #pragma unroll
        for (int t = 0; t < 9; t++) {
            const int ky = t/3, kx = t%3;
            const int wbase = (t*32 + c8)*64 + wlane;
            unsigned ah[2][4], al[2][4];
            #pragma unroll
            for (int m = 0; m < 2; m++) {
                const int wb = wbase + m*16;
                ah[m][0] = __float_as_uint(__ldg(&g_wt2hi[wb]));
                ah[m][1] = __float_as_uint(__ldg(&g_wt2hi[wb+8]));
                ah[m][2] = __float_as_uint(__ldg(&g_wt2hi[wb+256]));
                ah[m][3] = __float_as_uint(__ldg(&g_wt2hi[wb+264]));
                al[m][0] = __float_as_uint(__ldg(&g_wt2lo[wb]));
                al[m][1] = __float_as_uint(__ldg(&g_wt2lo[wb+8]));
                al[m][2] = __float_as_uint(__ldg(&g_wt2lo[wb+256]));
                al[m][3] = __float_as_uint(__ldg(&g_wt2lo[wb+264]));
            }
            const int bstep = c8*324 + blane + kx;
            #pragma unroll
            for (int nt = 0; nt < 8; nt++) {
                const int ry = nt >> 1, xh = nt & 1;
                const int ba = bstep + (y0+ry+ky)*18 + xh*8;
                unsigned bh[2], bl[2];
                bh[0] = __float_as_uint(in_hi[ba]);
                bh[1] = __float_as_uint(in_hi[ba + 4*324]);
                bl[0] = __float_as_uint(in_lo[ba]);
                bl[1] = __float_as_uint(in_lo[ba + 4*324]);
                #pragma unroll
                for (int m = 0; m < 2; m++) {
                    mma_tf32(c[m][nt], ah[m], bh);
                    mma_tf32(c[m][nt], ah[m], bl);
                    mma_tf32(c[m][nt], al[m], bh);
                }
            }
        }
    }

    float* outp = g_h2 + b*4096;
    #pragma unroll
    for (int m = 0; m < 2; m++) {
        #pragma unroll
        for (int h = 0; h < 2; h++) {
            const int oc = ocm + m*16 + h*8 + g;
            const float bv = __ldg(&bias[oc]);
            const int k0 = h*2;
            #pragma unroll
            for (int pr = 0; pr < 2; pr++) {
                #pragma unroll
                for (int xh = 0; xh < 2; xh++) {
                    const int nta = (2*pr)*2 + xh, ntb = nta + 2;
                    float v = fmaxf(fmaxf(c[m][nta][k0], c[m][nta][k0+1]),
                                    fmaxf(c[m][ntb][k0], c[m][ntb][k0+1]));
                    outp[oc*64 + (posg*2+pr)*8 + xh*4 + tig] = fmaxf(v + bv, 0.f);
                }
            }
        }
    }
}

// ---------------- conv3: tensor-core 3xTF32 tap-GEMM (R6/R10 version) ----------------
// 2 img/block, 256 thr = 8 warps = 2 img x 4 ocg(32 oc); each warp: all 64 pos.
#define C3_SMEM (2*6400*2*4)
__global__ void __launch_bounds__(256) k_conv3t(const float* __restrict__ bias) {
    extern __shared__ float sm[];
    const int b0 = blockIdx.x*2, tid = threadIdx.x;
    for (int i = tid; i < 12800; i += 256) { sm[i] = 0.f; sm[12800 + i] = 0.f; }
    __syncthreads();
    for (int i = tid; i < 8192; i += 256) {
        int img = i >> 12, rem = i & 4095;
        int ci = rem >> 6, r2 = rem & 63;
        float v = g_h2[(b0+img)*4096 + rem];
        float hi = tf32_hi(v);
        int d = img*6400 + ci*100 + ((r2>>3)+1)*10 + (r2&7) + 1;
        sm[d] = hi; sm[12800 + d] = v - hi;
    }
    __syncthreads();

    const int lane = tid & 31, wrp = tid >> 5;
    const int g = lane >> 2, tig = lane & 3;
    const int img = wrp >> 2, ocg = wrp & 3;
    const int ocm = ocg*32;
    const float* in_hi = sm + img*6400;
    const float* in_lo = sm + 12800 + img*6400;

    float c[2][8][4];
    #pragma unroll
    for (int m = 0; m < 2; m++)
        #pragma unroll
        for (int nt = 0; nt < 8; nt++)
            #pragma unroll
            for (int k = 0; k < 4; k++) c[m][nt][k] = 0.f;

    const int blane = tig*100 + g;
    const int wlane = tig*128 + ocm + g;

    for (int c8 = 0; c8 < 64; c8 += 8) {
        #pragma unroll
        for (int t = 0; t < 9; t++) {
            const int ky = t/3, kx = t%3;
            const int wbase = (t*64 + c8)*128 + wlane;
            unsigned ah[2][4], al[2][4];
            #pragma unroll
            for (int m = 0; m < 2; m++) {
                const int wb = wbase + m*16;
                ah[m][0] = __float_as_uint(__ldg(&g_wt3hi[wb]));
                ah[m][1] = __float_as_uint(__ldg(&g_wt3hi[wb+8]));
                ah[m][2] = __float_as_uint(__ldg(&g_wt3hi[wb+512]));
                ah[m][3] = __float_as_uint(__ldg(&g_wt3hi[wb+520]));
                al[m][0] = __float_as_uint(__ldg(&g_wt3lo[wb]));
                al[m][1] = __float_as_uint(__ldg(&g_wt3lo[wb+8]));
                al[m][2] = __float_as_uint(__ldg(&g_wt3lo[wb+512]));
                al[m][3] = __float_as_uint(__ldg(&g_wt3lo[wb+520]));
            }
            const int bstep = c8*100 + blane + kx;
            #pragma unroll
            for (int nt = 0; nt < 8; nt++) {
                const int ba = bstep + (nt+ky)*10;
                unsigned bh[2], bl[2];
                bh[0] = __float_as_uint(in_hi[ba]);
                bh[1] = __float_as_uint(in_hi[ba + 4*100]);
                bl[0] = __float_as_uint(in_lo[ba]);
                bl[1] = __float_as_uint(in_lo[ba + 4*100]);
                #pragma unroll
                for (int m = 0; m < 2; m++) {
                    mma_tf32(c[m][nt], ah[m], bh);
                    mma_tf32(c[m][nt], ah[m], bl);
                    mma_tf32(c[m][nt], al[m], bh);
                }
            }
        }
    }

    float* outp = g_h3 + (b0+img)*2048;
    #pragma unroll
    for (int m = 0; m < 2; m++) {
        #pragma unroll
        for (int h = 0; h < 2; h++) {
            const int oc = ocm + m*16 + h*8 + g;
            const float bv = __ldg(&bias[oc]);
            const int k0 = h*2;
            #pragma unroll
            for (int py = 0; py < 4; py++) {
                float v = fmaxf(fmaxf(c[m][2*py][k0], c[m][2*py][k0+1]),
                                fmaxf(c[m][2*py+1][k0], c[m][2*py+1][k0+1]));
                outp[oc*16 + py*4 + tig] = fmaxf(v + bv, 0.f);
            }
        }
    }
}

// ---------------- fc: [B,2048] @ [2048,256] (FFMA) ----------------
__global__ void __launch_bounds__(256) k_fc(const float* __restrict__ fcw,
                                            const float* __restrict__ fcb) {
    __shared__ float hs[32*256];
    const int bt = blockIdx.x*32, tid = threadIdx.x;
    const int tx = tid & 63, ty = tid >> 6;
    float acc[8][4];
    #pragma unroll
    for (int i = 0; i < 8; i++) { acc[i][0]=acc[i][1]=acc[i][2]=acc[i][3]=0.f; }
    for (int kc = 0; kc < 8; kc++) {
        __syncthreads();
        for (int i = tid; i < 8192; i += 256) {
            int rr = i >> 8, c = i & 255;
            hs[i] = g_h3[(bt+rr)*2048 + kc*256 + c];
        }
        __syncthreads();
        for (int d = 0; d < 256; d++) {
            float4 wv = *(const float4*)&fcw[(kc*256+d)*256 + tx*4];
            #pragma unroll
            for (int i = 0; i < 8; i++) {
                float f = hs[(ty*8+i)*256 + d];
                acc[i][0] += f*wv.x; acc[i][1] += f*wv.y;
                acc[i][2] += f*wv.z; acc[i][3] += f*wv.w;
            }
        }
    }
    float4 bb = *(const float4*)&fcb[tx*4];
    #pragma unroll
    for (int i = 0; i < 8; i++) {
        float* o = &g_feat[(bt+ty*8+i)*256 + tx*4];
        o[0] = acc[i][0]+bb.x; o[1] = acc[i][1]+bb.y;
        o[2] = acc[i][2]+bb.z; o[3] = acc[i][3]+bb.w;
    }
}

// ---------------- gate: logits, top-2, softmax, counts ----------------
__global__ void __launch_bounds__(256) k_gate(const float* __restrict__ gw,
                                              const float* __restrict__ gb) {
    __shared__ float fs[16*256];
    __shared__ float ls[16*17];
    const int b0 = blockIdx.x*16, tid = threadIdx.x;
    for (int i = tid; i < 4096; i += 256) fs[i] = g_feat[b0*256 + i];
    __syncthreads();
    const int t = tid >> 4, e = tid & 15;
    float acc = gb[e];
    for (int d = 0; d < 256; d++) acc += fs[t*256+d]*__ldg(&gw[d*16+e]);
    ls[t*17+e] = acc;
    __syncthreads();
    if (e == 0) {
        const float* l = &ls[t*17];
        int i1 = 0; float v1 = l[0];
        #pragma unroll
        for (int i = 1; i < 16; i++) if (l[i] > v1) { v1 = l[i]; i1 = i; }
        int i2 = -1; float v2 = -1e30f;
        #pragma unroll
        for (int i = 0; i < 16; i++) if (i != i1 && l[i] > v2) { v2 = l[i]; i2 = i; }
        float e2 = expf(v2 - v1);
        float inv = 1.0f/(1.0f + e2);
        float g1 = inv, g2 = e2*inv;
        int b = b0 + t;
        g_tidx[b*2] = i1;  g_tidx[b*2+1] = i2;
        g_tg[b*2]   = g1;  g_tg[b*2+1]   = g2;
        atomicAdd(&g_gatesum[i1], g1);
        atomicAdd(&g_gatesum[i2], g2);
        atomicAdd(&g_counts[i1], 1);
        atomicAdd(&g_counts[i2], 1);
    }
}

// ---------------- scan offsets + lb_loss ----------------
__global__ void k_scan(float* d_out, int out_size) {
    if (threadIdx.x == 0) {
        int off = 0;
        for (int e = 0; e < 16; e++) {
            g_offsets[e] = off; g_cursor[e] = off; off += g_counts[e];
        }
        float loss = 0.f;
        for (int e = 0; e < 16; e++) {
            float di = g_gatesum[e] / (float)BATCH;
            loss += di * logf(di + 1e-8f);
        }
        if (out_size > BATCH*NCLS) d_out[BATCH*NCLS] = loss;
    }
}

// ---------------- scatter tokens into expert-grouped lists ----------------
__global__ void k_scatter() {
    int s = blockIdx.x*256 + threadIdx.x;
    int e = g_tidx[s];
    int pos = atomicAdd(&g_cursor[e], 1);
    g_list_b[pos] = s >> 1;
    g_list_g[pos] = g_tg[s];
    g_slotpos[s] = pos;
}

// ---------------- expert pass A (MMA): h1 = relu(feat @ w1 + b1) ----------------
#define GE_SMEM (2*256*68*4)
__global__ void __launch_bounds__(256) k_e1m(const float* __restrict__ b1) {
    const int e = blockIdx.y;
    const int cnt = g_counts[e];
    const int ts = blockIdx.x*64;
    if (ts >= cnt) return;
    const int off = g_offsets[e];
    const int rows = min(64, cnt - ts);
    extern __shared__ float sm[];
    float* smh = sm;
    float* sml = sm + 256*68;
    const int tid = threadIdx.x;
    for (int i = tid; i < 64*256; i += 256) {
        int rr = i >> 8, cc = i & 255;
        float v = (rr < rows) ? g_feat[g_list_b[off+ts+rr]*256 + cc] : 0.f;
        float h = tf32_hi(v);
        smh[cc*68 + rr] = h; sml[cc*68 + rr] = v - h;
    }
    __syncthreads();
    const int lane = tid & 31, wrp = tid >> 5;
    const int g = lane >> 2, tig = lane & 3;
    const int mg = wrp >> 2, ng = wrp & 3;
    const float* Whi = g_e1hi + e*262144;
    const float* Wlo = g_e1lo + e*262144;

    for (int np = 0; np < 4; np++) {
        const int ncol = np*256 + ng*64;
        float c[2][8][4];
        #pragma unroll
        for (int mm = 0; mm < 2; mm++)
            #pragma unroll
            for (int nt = 0; nt < 8; nt++)
                #pragma unroll
                for (int k = 0; k < 4; k++) c[mm][nt][k] = 0.f;
        for (int k8 = 0; k8 < 256; k8 += 8) {
            unsigned ah[2][4], al[2][4];
            #pragma unroll
            for (int mm = 0; mm < 2; mm++) {
                const int mb = mg*32 + mm*16 + g;
                const int a0 = (k8+tig)*68 + mb;
                const int a1 = (k8+tig+4)*68 + mb;
                ah[mm][0] = __float_as_uint(smh[a0]);
                ah[mm][1] = __float_as_uint(smh[a0+8]);
                ah[mm][2] = __float_as_uint(smh[a1]);
                ah[mm][3] = __float_as_uint(smh[a1+8]);
                al[mm][0] = __float_as_uint(sml[a0]);
                al[mm][1] = __float_as_uint(sml[a0+8]);
                al[mm][2] = __float_as_uint(sml[a1]);
                al[mm][3] = __float_as_uint(sml[a1+8]);
            }
            #pragma unroll
            for (int nt = 0; nt < 8; nt++) {
                const int col = ncol + nt*8 + g;
                const int kb = (k8+tig)*1024 + col;
                unsigned bh[2], bl[2];
                bh[0] = __float_as_uint(__ldg(&Whi[kb]));
                bh[1] = __float_as_uint(__ldg(&Whi[kb + 4*1024]));
                bl[0] = __float_as_uint(__ldg(&Wlo[kb]));
                bl[1] = __float_as_uint(__ldg(&Wlo[kb + 4*1024]));
                #pragma unroll
                for (int mm = 0; mm < 2; mm++) {
                    mma_tf32(c[mm][nt], ah[mm], bh);
                    mma_tf32(c[mm][nt], ah[mm], bl);
                    mma_tf32(c[mm][nt], al[mm], bh);
                }
            }
        }
        #pragma unroll
        for (int mm = 0; mm < 2; mm++)
            #pragma unroll
            for (int h = 0; h < 2; h++) {
                const int row = mg*32 + mm*16 + h*8 + g;
                if (row < rows) {
                    const int slot = off + ts + row;
                    #pragma unroll
                    for (int nt = 0; nt < 8; nt++) {
                        const int col = ncol + nt*8 + tig*2;
                        float v0 = c[mm][nt][h*2]   + __ldg(&b1[e*1024+col]);
                        float v1 = c[mm][nt][h*2+1] + __ldg(&b1[e*1024+col+1]);
                        g_h1e[slot*1024 + col]   = fmaxf(v0, 0.f);
                        g_h1e[slot*1024 + col+1] = fmaxf(v1, 0.f);
                    }
                }
            }
    }
}

// ---------------- expert pass B (MMA): eo = gate*(h1 @ w2 + b2) ----------------
__global__ void __launch_bounds__(256) k_e2m(const float* __restrict__ b2) {
    const int e = blockIdx.y;
    const int cnt = g_counts[e];
    const int ts = blockIdx.x*64;
    if (ts >= cnt) return;
    const int off = g_offsets[e];
    const int rows = min(64, cnt - ts);
    extern __shared__ float sm[];
    float* smh = sm;
    float* sml = sm + 256*68;
    const int tid = threadIdx.x;
    const int lane = tid & 31, wrp = tid >> 5;
    const int g = lane >> 2, tig = lane & 3;
    const int mg = wrp >> 2, ng = wrp & 3;
    const float* Whi = g_e2hi + e*262144;
    const float* Wlo = g_e2lo + e*262144;

    float c[2][8][4];
    #pragma unroll
    for (int mm = 0; mm < 2; mm++)
        #pragma unroll
        for (int nt = 0; nt < 8; nt++)
            #pragma unroll
            for (int k = 0; k < 4; k++) c[mm][nt][k] = 0.f;

    for (int st = 0; st < 4; st++) {
        __syncthreads();
        for (int i = tid; i < 64*256; i += 256) {
            int rr = i >> 8, cc = i & 255;
            float v = (rr < rows) ? g_h1e[(off+ts+rr)*1024 + st*256 + cc] : 0.f;
            float h = tf32_hi(v);
            smh[cc*68 + rr] = h; sml[cc*68 + rr] = v - h;
        }
        __syncthreads();
        for (int k8 = 0; k8 < 256; k8 += 8) {
            unsigned ah[2][4], al[2][4];
            #pragma unroll
            for (int mm = 0; mm < 2; mm++) {
                const int mb = mg*32 + mm*16 + g;
                const int a0 = (k8+tig)*68 + mb;
                const int a1 = (k8+tig+4)*68 + mb;
                ah[mm][0] = __float_as_uint(smh[a0]);
                ah[mm][1] = __float_as_uint(smh[a0+8]);
                ah[mm][2] = __float_as_uint(smh[a1]);
                ah[mm][3] = __float_as_uint(smh[a1+8]);
                al[mm][0] = __float_as_uint(sml[a0]);
                al[mm][1] = __float_as_uint(sml[a0+8]);
                al[mm][2] = __float_as_uint(sml[a1]);
                al[mm][3] = __float_as_uint(sml[a1+8]);
            }
            #pragma unroll
            for (int nt = 0; nt < 8; nt++) {
                const int col = ng*64 + nt*8 + g;
                const int kb = (st*256 + k8 + tig)*256 + col;
                unsigned bh[2], bl[2];
                bh[0] = __float_as_uint(__ldg(&Whi[kb]));
                bh[1] = __float_as_uint(__ldg(&Whi[kb + 4*256]));
                bl[0] = __float_as_uint(__ldg(&Wlo[kb]));
                bl[1] = __float_as_uint(__ldg(&Wlo[kb + 4*256]));
                #pragma unroll
                for (int mm = 0; mm < 2; mm++) {
                    mma_tf32(c[mm][nt], ah[mm], bh);
                    mma_tf32(c[mm][nt], ah[mm], bl);
                    mma_tf32(c[mm][nt], al[mm], bh);
                }
            }
        }
    }
    #pragma unroll
    for (int mm = 0; mm < 2; mm++)
        #pragma unroll
        for (int h = 0; h < 2; h++) {
            const int row = mg*32 + mm*16 + h*8 + g;
            if (row < rows) {
                const int slot = off + ts + row;
                const float gt = g_list_g[slot];
                #pragma unroll
                for (int nt = 0; nt < 8; nt++) {
                    const int col = ng*64 + nt*8 + tig*2;
                    float v0 = c[mm][nt][h*2]   + __ldg(&b2[e*256+col]);
                    float v1 = c[mm][nt][h*2+1] + __ldg(&b2[e*256+col+1]);
                    g_eo[slot*256 + col]   = gt*v0;
                    g_eo[slot*256 + col+1] = gt*v1;
                }
            }
        }
}

// ---------------- combine + residual + LayerNorm ----------------
__global__ void __launch_bounds__(256) k_ln(const float* __restrict__ lng,
                                            const float* __restrict__ lnb) {
    const int b = blockIdx.x, tid = threadIdx.x;
    const int p0 = g_slotpos[b*2], p1 = g_slotpos[b*2+1];
    float y = g_eo[p0*256+tid] + g_eo[p1*256+tid] + g_feat[b*256+tid];
    __shared__ float red[16];
    __shared__ float mu_s, rstd_s;
    float s = y, s2 = y*y;
    #pragma unroll
    for (int o = 16; o > 0; o >>= 1) {
        s  += __shfl_xor_sync(0xffffffffu, s,  o);
        s2 += __shfl_xor_sync(0xffffffffu, s2, o);
    }
    if ((tid & 31) == 0) { red[tid>>5] = s; red[8 + (tid>>5)] = s2; }
    __syncthreads();
    if (tid == 0) {
        float S = 0.f, S2 = 0.f;
        #pragma unroll
        for (int i = 0; i < 8; i++) { S += red[i]; S2 += red[8+i]; }
        float mu = S/256.f;
        mu_s = mu;
        rstd_s = rsqrtf(S2/256.f - mu*mu + 1e-5f);
    }
    __syncthreads();
    g_y[b*256+tid] = (y - mu_s)*rstd_s*lng[tid] + lnb[tid];
}

// ---------------- output projection: [B,256] @ [256,1000] (FFMA) ----------------
__global__ void __launch_bounds__(256) k_out(const float* __restrict__ ow,
                                             const float* __restrict__ ob,
                                             float* __restrict__ out) {
    __shared__ float ys[32*256];
    const int bt = blockIdx.y*32, cb = blockIdx.x*256, tid = threadIdx.x;
    for (int i = tid; i < 8192; i += 256) ys[i] = g_y[bt*256 + i];
    __syncthreads();
    const int tx = tid & 63, ty = tid >> 6;
    const int c = cb + tx*4;
    bool v0 = c < NCLS, v1 = c+1 < NCLS, v2 = c+2 < NCLS, v3 = c+3 < NCLS;
    float acc[8][4];
    #pragma unroll
    for (int i = 0; i < 8; i++) { acc[i][0]=acc[i][1]=acc[i][2]=acc[i][3]=0.f; }
    for (int d = 0; d < 256; d++) {
        const float* wr = ow + d*NCLS;
        float w0 = v0 ? wr[c]   : 0.f;
        float w1 = v1 ? wr[c+1] : 0.f;
        float w2 = v2 ? wr[c+2] : 0.f;
        float w3 = v3 ? wr[c+3] : 0.f;
        #pragma unroll
        for (int i = 0; i < 8; i++) {
            float f = ys[(ty*8+i)*256 + d];
            acc[i][0] += f*w0; acc[i][1] += f*w1;
            acc[i][2] += f*w2; acc[i][3] += f*w3;
        }
    }
    float b0 = v0 ? ob[c] : 0.f, b1 = v1 ? ob[c+1] : 0.f;
    float b2 = v2 ? ob[c+2] : 0.f, b3 = v3 ? ob[c+3] : 0.f;
    #pragma unroll
    for (int i = 0; i < 8; i++) {
        float* o = out + (bt+ty*8+i)*NCLS;
        if (v0) o[c]   = acc[i][0] + b0;
        if (v1) o[c+1] = acc[i][1] + b1;
        if (v2) o[c+2] = acc[i][2] + b2;
        if (v3) o[c+3] = acc[i][3] + b3;
    }
}

// ---------------- launch ----------------
extern "C" void kernel_launch(void* const* d_in, const int* in_sizes, int n_in,
                              void* d_out, int out_size) {
    const float* x   = (const float*)d_in[0];
    const float* c1w = (const float*)d_in[1];
    const float* c1b = (const float*)d_in[2];
    const float* c2w = (const float*)d_in[3];
    const float* c2b = (const float*)d_in[4];
    const float* c3w = (const float*)d_in[5];
    const float* c3b = (const float*)d_in[6];
    const float* fcw = (const float*)d_in[7];
    const float* fcb = (const float*)d_in[8];
    const float* gw  = (const float*)d_in[9];
    const float* gb  = (const float*)d_in[10];
    const float* ew1 = (const float*)d_in[11];
    const float* eb1 = (const float*)d_in[12];
    const float* ew2 = (const float*)d_in[13];
    const float* eb2 = (const float*)d_in[14];
    const float* lng = (const float*)d_in[15];
    const float* lnb = (const float*)d_in[16];
    const float* ow  = (const float*)d_in[17];
    const float* ob  = (const float*)d_in[18];
    float* out = (float*)d_out;

    cudaFuncSetAttribute(k_conv2t, cudaFuncAttributeMaxDynamicSharedMemorySize, C2_SMEM);
    cudaFuncSetAttribute(k_conv3t, cudaFuncAttributeMaxDynamicSharedMemorySize, C3_SMEM);
    cudaFuncSetAttribute(k_e1m, cudaFuncAttributeMaxDynamicSharedMemorySize, GE_SMEM);
    cudaFuncSetAttribute(k_e2m, cudaFuncAttributeMaxDynamicSharedMemorySize, GE_SMEM);

    k_zero<<<1, 32>>>();
    k_wtrans<<<288, 256>>>(c2w, c3w);
    k_wprep<<<2048, 256>>>(ew1, ew2);
    k_conv1<<<BATCH/2, 512>>>(x, c1w, c1b);
    k_conv2t<<<BATCH, 256, C2_SMEM>>>(c2b);
    k_conv3t<<<BATCH/2, 256, C3_SMEM>>>(c3b);
    k_fc<<<BATCH/32, 256>>>(fcw, fcb);
    k_gate<<<BATCH/16, 256>>>(gw, gb);
    k_scan<<<1, 32>>>(out, out_size);
    k_scatter<<<BATCH*2/256, 256>>>();
    dim3 ge(128, 16);
    k_e1m<<<ge, 256, GE_SMEM>>>(eb1);
    k_e2m<<<ge, 256, GE_SMEM>>>(eb2);
    k_ln<<<BATCH, 256>>>(lng, lnb);
    dim3 go(4, BATCH/32);
    k_out<<<go, 256>>>(ow, ob, out);
}

// round 14
// speedup vs baseline: 1.0564x; 1.0001x over previous
#include <cuda_runtime.h>
#include <math.h>

#define BATCH 4096
#define NCLS  1000

// ---------------- scratch (device globals; no dynamic allocation) ----------------
__device__ float g_h1[BATCH*32*16*16];   // conv1 pooled out  [B,32,16,16]
__device__ float g_h2[BATCH*64*8*8];     // conv2 pooled out  [B,64,8,8]
__device__ float g_h3[BATCH*2048];       // conv3 pooled flat [B,2048]
__device__ float g_feat[BATCH*256];      // fc out            [B,256]
__device__ float g_y[BATCH*256];         // layernorm out     [B,256]
__device__ int   g_tidx[BATCH*2];        // top2 expert idx
__device__ float g_tg[BATCH*2];          // top2 gate weights
__device__ float g_gatesum[16];
__device__ int   g_counts[16];
__device__ int   g_offsets[16];
__device__ int   g_cursor[16];
__device__ int   g_list_b[BATCH*2];      // token id per grouped slot
__device__ float g_list_g[BATCH*2];      // gate weight per grouped slot
__device__ int   g_slotpos[BATCH*2];     // (b,k) -> grouped slot
__device__ float g_h1e[BATCH*2*1024];    // expert hidden per slot
__device__ float g_eo[BATCH*2*256];      // gate-scaled expert out per slot
// conv weights transposed to [tap][ci][oc], split hi/lo tf32
__device__ float g_wt2hi[9*32*64];
__device__ float g_wt2lo[9*32*64];
__device__ float g_wt3hi[9*64*128];
__device__ float g_wt3lo[9*64*128];
// expert weights split hi/lo (layout already [e][k][n])
__device__ float g_e1hi[16*262144];
__device__ float g_e1lo[16*262144];
__device__ float g_e2hi[16*262144];
__device__ float g_e2lo[16*262144];

// ---------------- tf32 helpers ----------------
__device__ __forceinline__ float tf32_hi(float x) {
    return __uint_as_float(__float_as_uint(x) & 0xFFFFE000u);
}

__device__ __forceinline__ void mma_tf32(float* c, const unsigned* a, const unsigned* b) {
    asm volatile(
        "mma.sync.aligned.m16n8k8.row.col.f32.tf32.tf32.f32 "
        "{%0,%1,%2,%3}, {%4,%5,%6,%7}, {%8,%9}, {%0,%1,%2,%3};"
        : "+f"(c[0]), "+f"(c[1]), "+f"(c[2]), "+f"(c[3])
        : "r"(a[0]), "r"(a[1]), "r"(a[2]), "r"(a[3]), "r"(b[0]), "r"(b[1]));
}

// ---------------- init ----------------
__global__ void k_zero() {
    int t = threadIdx.x;
    if (t < 16) { g_gatesum[t] = 0.f; g_counts[t] = 0; }
}

// ---------------- weight transpose: OIHW -> [tap][ci][oc], hi/lo split ----------------
__global__ void k_wtrans(const float* __restrict__ c2w, const float* __restrict__ c3w) {
    int idx = blockIdx.x*256 + threadIdx.x;
    if (idx < 18432) {          // conv2: [64][32][9]
        int oc = idx / 288, rem = idx % 288;
        int ci = rem / 9, t = rem % 9;
        float v = c2w[idx];
        float hi = tf32_hi(v);
        int d = (t*32 + ci)*64 + oc;
        g_wt2hi[d] = hi; g_wt2lo[d] = v - hi;
    }
    if (idx < 73728) {          // conv3: [128][64][9]
        int oc = idx / 576, rem = idx % 576;
        int ci = rem / 9, t = rem % 9;
        float v = c3w[idx];
        float hi = tf32_hi(v);
        int d = (t*64 + ci)*128 + oc;
        g_wt3hi[d] = hi; g_wt3lo[d] = v - hi;
    }
}

// ---------------- expert weight hi/lo split ----------------
__global__ void k_wprep(const float* __restrict__ w1, const float* __restrict__ w2) {
    for (int i = blockIdx.x*256 + threadIdx.x; i < 16*262144; i += gridDim.x*256) {
        float v = w1[i]; float h = tf32_hi(v);
        g_e1hi[i] = h; g_e1lo[i] = v - h;
        v = w2[i]; h = tf32_hi(v);
        g_e2hi[i] = h; g_e2lo[i] = v - h;
    }
}

// ---------------- conv1: [B,3,32,32] -> pool -> relu -> [B,32,16,16] ----------------
// 2 img/block; reg-capped to 64 so 2 CTAs/SM (32 warps) fit.
__global__ void __launch_bounds__(512, 2) k_conv1(const float* __restrict__ x,
                                                  const float* __restrict__ w,
                                                  const float* __restrict__ bias) {
    __shared__ float xs[2*3*34*34];
    __shared__ float ws[27*36];
    __shared__ float bs[32];
    const int b0 = blockIdx.x*2, tid = threadIdx.x;
    for (int i = tid; i < 2*3468; i += 512) xs[i] = 0.f;
    if (tid < 32) bs[tid] = bias[tid];
    __syncthreads();
    for (int i = tid; i < 2*3072; i += 512) {
        int img = i / 3072, rem = i % 3072;
        int ci = rem >> 10, r2 = rem & 1023;
        xs[img*3468 + ci*1156 + ((r2>>5)+1)*34 + (r2&31) + 1] = x[(b0+img)*3072 + rem];
    }
    for (int i = tid; i < 864; i += 512)
        ws[(i%27)*36 + (i/27)] = w[i];
    __syncthreads();

    const int img = tid >> 8, t = tid & 255;
    const int py = t >> 4, px = t & 15;
    const float* xsI = xs + img*3468;
    float* outp = g_h1 + (b0+img)*8192;
    for (int cb = 0; cb < 32; cb += 8) {
        float acc[8][4];
        #pragma unroll
        for (int j = 0; j < 8; j++) { acc[j][0]=acc[j][1]=acc[j][2]=acc[j][3]=0.f; }
        #pragma unroll
        for (int ci = 0; ci < 3; ci++) {
            #pragma unroll
            for (int ky = 0; ky < 3; ky++) {
                #pragma unroll
                for (int kx = 0; kx < 3; kx++) {
                    const int kk = ci*9 + ky*3 + kx;
                    float wv[8];
                    *(float4*)&wv[0] = *(const float4*)&ws[kk*36 + cb];
                    *(float4*)&wv[4] = *(const float4*)&ws[kk*36 + cb + 4];
                    float iv[4];
                    #pragma unroll
                    for (int dy = 0; dy < 2; dy++)
                        #pragma unroll
                        for (int dx = 0; dx < 2; dx++)
                            iv[dy*2+dx] = xsI[ci*1156 + (2*py+dy+ky)*34 + (2*px+dx+kx)];
                    #pragma unroll
                    for (int j = 0; j < 8; j++)
                        #pragma unroll
                        for (int p = 0; p < 4; p++)
                            acc[j][p] += wv[j]*iv[p];
                }
            }
        }
        #pragma unroll
        for (int j = 0; j < 8; j++) {
            float m = fmaxf(fmaxf(acc[j][0],acc[j][1]), fmaxf(acc[j][2],acc[j][3]));
            outp[(cb+j)*256 + t] = fmaxf(m + bs[cb+j], 0.f);
        }
    }
}

// ---------------- conv2: tensor-core 3xTF32 tap-GEMM (R6/R10 version) ----------------
// 1 img/block, 256 thr = 8 warps = 2 ocg(32 oc) x 4 posg(4 rows y).
#define C2_SMEM (2*10368*4)
__global__ void __launch_bounds__(256) k_conv2t(const float* __restrict__ bias) {
    extern __shared__ float sm[];
    float* in_hi = sm;            // 32*18*18 padded
    float* in_lo = sm + 10368;
    const int b = blockIdx.x, tid = threadIdx.x;
    for (int i = tid; i < 10368; i += 256) { in_hi[i] = 0.f; in_lo[i] = 0.f; }
    __syncthreads();
    for (int i = tid; i < 8192; i += 256) {
        int ci = i >> 8, r2 = i & 255;
        float v = g_h1[b*8192 + i];
        float hi = tf32_hi(v);
        int d = ci*324 + ((r2>>4)+1)*18 + (r2&15) + 1;
        in_hi[d] = hi; in_lo[d] = v - hi;
    }
    __syncthreads();

    const int lane = tid & 31, wrp = tid >> 5;
    const int g = lane >> 2, tig = lane & 3;
    const int ocg = wrp >> 2, posg = wrp & 3;
    const int y0 = posg*4;
    const int ocm = ocg*32;

    float c[2][8][4];
    #pragma unroll
    for (int m = 0; m < 2; m++)
        #pragma unroll
        for (int nt = 0; nt < 8; nt++)
            #pragma unroll
            for (int k = 0; k < 4; k++) c[m][nt][k] = 0.f;

    const int blane = tig*324 + g;
    const int wlane = tig*64 + ocm + g;

    for (int c8 = 0; c8 < 32; c8 += 8) {
        #pragma unroll
        for (int t = 0; t < 9; t++) {
            const int ky = t/3, kx = t%3;
            const int wbase = (t*32 + c8)*64 + wlane;
            unsigned ah[2][4], al[2][4];
            #pragma unroll
            for (int m = 0; m < 2; m++) {
                const int wb = wbase + m*16;
                ah[m][0] = __float_as_uint(__ldg(&g_wt2hi[wb]));
                ah[m][1] = __float_as_uint(__ldg(&g_wt2hi[wb+8]));
                ah[m][2] = __float_as_uint(__ldg(&g_wt2hi[wb+256]));
                ah[m][3] = __float_as_uint(__ldg(&g_wt2hi[wb+264]));
                al[m][0] = __float_as_uint(__ldg(&g_wt2lo[wb]));
                al[m][1] = __float_as_uint(__ldg(&g_wt2lo[wb+8]));
                al[m][2] = __float_as_uint(__ldg(&g_wt2lo[wb+256]));
                al[m][3] = __float_as_uint(__ldg(&g_wt2lo[wb+264]));
            }
            const int bstep = c8*324 + blane + kx;
            #pragma unroll
            for (int nt = 0; nt < 8; nt++) {
                const int ry = nt >> 1, xh = nt & 1;
                const int ba = bstep + (y0+ry+ky)*18 + xh*8;
                unsigned bh[2], bl[2];
                bh[0] = __float_as_uint(in_hi[ba]);
                bh[1] = __float_as_uint(in_hi[ba + 4*324]);
                bl[0] = __float_as_uint(in_lo[ba]);
                bl[1] = __float_as_uint(in_lo[ba + 4*324]);
                #pragma unroll
                for (int m = 0; m < 2; m++) {
                    mma_tf32(c[m][nt], ah[m], bh);
                    mma_tf32(c[m][nt], ah[m], bl);
                    mma_tf32(c[m][nt], al[m], bh);
                }
            }
        }
    }

    float* outp = g_h2 + b*4096;
    #pragma unroll
    for (int m = 0; m < 2; m++) {
        #pragma unroll
        for (int h = 0; h < 2; h++) {
            const int oc = ocm + m*16 + h*8 + g;
            const float bv = __ldg(&bias[oc]);
            const int k0 = h*2;
            #pragma unroll
            for (int pr = 0; pr < 2; pr++) {
                #pragma unroll
                for (int xh = 0; xh < 2; xh++) {
                    const int nta = (2*pr)*2 + xh, ntb = nta + 2;
                    float v = fmaxf(fmaxf(c[m][nta][k0], c[m][nta][k0+1]),
                                    fmaxf(c[m][ntb][k0], c[m][ntb][k0+1]));
                    outp[oc*64 + (posg*2+pr)*8 + xh*4 + tig] = fmaxf(v + bv, 0.f);
                }
            }
        }
    }
}

// ---------------- conv3: tensor-core 3xTF32 tap-GEMM (R6/R10 version) ----------------
// 2 img/block, 256 thr = 8 warps = 2 img x 4 ocg(32 oc); each warp: all 64 pos.
#define C3_SMEM (2*6400*2*4)
__global__ void __launch_bounds__(256) k_conv3t(const float* __restrict__ bias) {
    extern __shared__ float sm[];
    const int b0 = blockIdx.x*2, tid = threadIdx.x;
    for (int i = tid; i < 12800; i += 256) { sm[i] = 0.f; sm[12800 + i] = 0.f; }
    __syncthreads();
    for (int i = tid; i < 8192; i += 256) {
        int img = i >> 12, rem = i & 4095;
        int ci = rem >> 6, r2 = rem & 63;
        float v = g_h2[(b0+img)*4096 + rem];
        float hi = tf32_hi(v);
        int d = img*6400 + ci*100 + ((r2>>3)+1)*10 + (r2&7) + 1;
        sm[d] = hi; sm[12800 + d] = v - hi;
    }
    __syncthreads();

    const int lane = tid & 31, wrp = tid >> 5;
    const int g = lane >> 2, tig = lane & 3;
    const int img = wrp >> 2, ocg = wrp & 3;
    const int ocm = ocg*32;
    const float* in_hi = sm + img*6400;
    const float* in_lo = sm + 12800 + img*6400;

    float c[2][8][4];
    #pragma unroll
    for (int m = 0; m < 2; m++)
        #pragma unroll
        for (int nt = 0; nt < 8; nt++)
            #pragma unroll
            for (int k = 0; k < 4; k++) c[m][nt][k] = 0.f;

    const int blane = tig*100 + g;
    const int wlane = tig*128 + ocm + g;

    for (int c8 = 0; c8 < 64; c8 += 8) {
        #pragma unroll
        for (int t = 0; t < 9; t++) {
            const int ky = t/3, kx = t%3;
            const int wbase = (t*64 + c8)*128 + wlane;
            unsigned ah[2][4], al[2][4];
            #pragma unroll
            for (int m = 0; m < 2; m++) {
                const int wb = wbase + m*16;
                ah[m][0] = __float_as_uint(__ldg(&g_wt3hi[wb]));
                ah[m][1] = __float_as_uint(__ldg(&g_wt3hi[wb+8]));
                ah[m][2] = __float_as_uint(__ldg(&g_wt3hi[wb+512]));
                ah[m][3] = __float_as_uint(__ldg(&g_wt3hi[wb+520]));
                al[m][0] = __float_as_uint(__ldg(&g_wt3lo[wb]));
                al[m][1] = __float_as_uint(__ldg(&g_wt3lo[wb+8]));
                al[m][2] = __float_as_uint(__ldg(&g_wt3lo[wb+512]));
                al[m][3] = __float_as_uint(__ldg(&g_wt3lo[wb+520]));
            }
            const int bstep = c8*100 + blane + kx;
            #pragma unroll
            for (int nt = 0; nt < 8; nt++) {
                const int ba = bstep + (nt+ky)*10;
                unsigned bh[2], bl[2];
                bh[0] = __float_as_uint(in_hi[ba]);
                bh[1] = __float_as_uint(in_hi[ba + 4*100]);
                bl[0] = __float_as_uint(in_lo[ba]);
                bl[1] = __float_as_uint(in_lo[ba + 4*100]);
                #pragma unroll
                for (int m = 0; m < 2; m++) {
                    mma_tf32(c[m][nt], ah[m], bh);
                    mma_tf32(c[m][nt], ah[m], bl);
                    mma_tf32(c[m][nt], al[m], bh);
                }
            }
        }
    }

    float* outp = g_h3 + (b0+img)*2048;
    #pragma unroll
    for (int m = 0; m < 2; m++) {
        #pragma unroll
        for (int h = 0; h < 2; h++) {
            const int oc = ocm + m*16 + h*8 + g;
            const float bv = __ldg(&bias[oc]);
            const int k0 = h*2;
            #pragma unroll
            for (int py = 0; py < 4; py++) {
                float v = fmaxf(fmaxf(c[m][2*py][k0], c[m][2*py][k0+1]),
                                fmaxf(c[m][2*py+1][k0], c[m][2*py+1][k0+1]));
                outp[oc*16 + py*4 + tig] = fmaxf(v + bv, 0.f);
            }
        }
    }
}

// ---------------- fc: [B,2048] @ [2048,256] (FFMA) ----------------
__global__ void __launch_bounds__(256) k_fc(const float* __restrict__ fcw,
                                            const float* __restrict__ fcb) {
    __shared__ float hs[32*256];
    const int bt = blockIdx.x*32, tid = threadIdx.x;
    const int tx = tid & 63, ty = tid >> 6;
    float acc[8][4];
    #pragma unroll
    for (int i = 0; i < 8; i++) { acc[i][0]=acc[i][1]=acc[i][2]=acc[i][3]=0.f; }
    for (int kc = 0; kc < 8; kc++) {
        __syncthreads();
        for (int i = tid; i < 8192; i += 256) {
            int rr = i >> 8, c = i & 255;
            hs[i] = g_h3[(bt+rr)*2048 + kc*256 + c];
        }
        __syncthreads();
        for (int d = 0; d < 256; d++) {
            float4 wv = *(const float4*)&fcw[(kc*256+d)*256 + tx*4];
            #pragma unroll
            for (int i = 0; i < 8; i++) {
                float f = hs[(ty*8+i)*256 + d];
                acc[i][0] += f*wv.x; acc[i][1] += f*wv.y;
                acc[i][2] += f*wv.z; acc[i][3] += f*wv.w;
            }
        }
    }
    float4 bb = *(const float4*)&fcb[tx*4];
    #pragma unroll
    for (int i = 0; i < 8; i++) {
        float* o = &g_feat[(bt+ty*8+i)*256 + tx*4];
        o[0] = acc[i][0]+bb.x; o[1] = acc[i][1]+bb.y;
        o[2] = acc[i][2]+bb.z; o[3] = acc[i][3]+bb.w;
    }
}

// ---------------- gate: logits, top-2, softmax, counts ----------------
__global__ void __launch_bounds__(256) k_gate(const float* __restrict__ gw,
                                              const float* __restrict__ gb) {
    __shared__ float fs[16*256];
    __shared__ float ls[16*17];
    const int b0 = blockIdx.x*16, tid = threadIdx.x;
    for (int i = tid; i < 4096; i += 256) fs[i] = g_feat[b0*256 + i];
    __syncthreads();
    const int t = tid >> 4, e = tid & 15;
    float acc = gb[e];
    for (int d = 0; d < 256; d++) acc += fs[t*256+d]*__ldg(&gw[d*16+e]);
    ls[t*17+e] = acc;
    __syncthreads();
    if (e == 0) {
        const float* l = &ls[t*17];
        int i1 = 0; float v1 = l[0];
        #pragma unroll
        for (int i = 1; i < 16; i++) if (l[i] > v1) { v1 = l[i]; i1 = i; }
        int i2 = -1; float v2 = -1e30f;
        #pragma unroll
        for (int i = 0; i < 16; i++) if (i != i1 && l[i] > v2) { v2 = l[i]; i2 = i; }
        float e2 = expf(v2 - v1);
        float inv = 1.0f/(1.0f + e2);
        float g1 = inv, g2 = e2*inv;
        int b = b0 + t;
        g_tidx[b*2] = i1;  g_tidx[b*2+1] = i2;
        g_tg[b*2]   = g1;  g_tg[b*2+1]   = g2;
        atomicAdd(&g_gatesum[i1], g1);
        atomicAdd(&g_gatesum[i2], g2);
        atomicAdd(&g_counts[i1], 1);
        atomicAdd(&g_counts[i2], 1);
    }
}

// ---------------- scan offsets + lb_loss ----------------
__global__ void k_scan(float* d_out, int out_size) {
    if (threadIdx.x == 0) {
        int off = 0;
        for (int e = 0; e < 16; e++) {
            g_offsets[e] = off; g_cursor[e] = off; off += g_counts[e];
        }
        float loss = 0.f;
        for (int e = 0; e < 16; e++) {
            float di = g_gatesum[e] / (float)BATCH;
            loss += di * logf(di + 1e-8f);
        }
        if (out_size > BATCH*NCLS) d_out[BATCH*NCLS] = loss;
    }
}

// ---------------- scatter tokens into expert-grouped lists ----------------
__global__ void k_scatter() {
    int s = blockIdx.x*256 + threadIdx.x;
    int e = g_tidx[s];
    int pos = atomicAdd(&g_cursor[e], 1);
    g_list_b[pos] = s >> 1;
    g_list_g[pos] = g_tg[s];
    g_slotpos[s] = pos;
}

// ---------------- expert pass A (MMA): h1 = relu(feat @ w1 + b1) ----------------
#define GE_SMEM (2*256*68*4)
__global__ void __launch_bounds__(256) k_e1m(const float* __restrict__ b1) {
    const int e = blockIdx.y;
    const int cnt = g_counts[e];
    const int ts = blockIdx.x*64;
    if (ts >= cnt) return;
    const int off = g_offsets[e];
    const int rows = min(64, cnt - ts);
    extern __shared__ float sm[];
    float* smh = sm;
    float* sml = sm + 256*68;
    const int tid = threadIdx.x;
    for (int i = tid; i < 64*256; i += 256) {
        int rr = i >> 8, cc = i & 255;
        float v = (rr < rows) ? g_feat[g_list_b[off+ts+rr]*256 + cc] : 0.f;
        float h = tf32_hi(v);
        smh[cc*68 + rr] = h; sml[cc*68 + rr] = v - h;
    }
    __syncthreads();
    const int lane = tid & 31, wrp = tid >> 5;
    const int g = lane >> 2, tig = lane & 3;
    const int mg = wrp >> 2, ng = wrp & 3;
    const float* Whi = g_e1hi + e*262144;
    const float* Wlo = g_e1lo + e*262144;

    for (int np = 0; np < 4; np++) {
        const int ncol = np*256 + ng*64;
        float c[2][8][4];
        #pragma unroll
        for (int mm = 0; mm < 2; mm++)
            #pragma unroll
            for (int nt = 0; nt < 8; nt++)
                #pragma unroll
                for (int k = 0; k < 4; k++) c[mm][nt][k] = 0.f;
        for (int k8 = 0; k8 < 256; k8 += 8) {
            unsigned ah[2][4], al[2][4];
            #pragma unroll
            for (int mm = 0; mm < 2; mm++) {
                const int mb = mg*32 + mm*16 + g;
                const int a0 = (k8+tig)*68 + mb;
                const int a1 = (k8+tig+4)*68 + mb;
                ah[mm][0] = __float_as_uint(smh[a0]);
                ah[mm][1] = __float_as_uint(smh[a0+8]);
                ah[mm][2] = __float_as_uint(smh[a1]);
                ah[mm][3] = __float_as_uint(smh[a1+8]);
                al[mm][0] = __float_as_uint(sml[a0]);
                al[mm][1] = __float_as_uint(sml[a0+8]);
                al[mm][2] = __float_as_uint(sml[a1]);
                al[mm][3] = __float_as_uint(sml[a1+8]);
            }
            #pragma unroll
            for (int nt = 0; nt < 8; nt++) {
                const int col = ncol + nt*8 + g;
                const int kb = (k8+tig)*1024 + col;
                unsigned bh[2], bl[2];
                bh[0] = __float_as_uint(__ldg(&Whi[kb]));
                bh[1] = __float_as_uint(__ldg(&Whi[kb + 4*1024]));
                bl[0] = __float_as_uint(__ldg(&Wlo[kb]));
                bl[1] = __float_as_uint(__ldg(&Wlo[kb + 4*1024]));
                #pragma unroll
                for (int mm = 0; mm < 2; mm++) {
                    mma_tf32(c[mm][nt], ah[mm], bh);
                    mma_tf32(c[mm][nt], ah[mm], bl);
                    mma_tf32(c[mm][nt], al[mm], bh);
                }
            }
        }
        #pragma unroll
        for (int mm = 0; mm < 2; mm++)
            #pragma unroll
            for (int h = 0; h < 2; h++) {
                const int row = mg*32 + mm*16 + h*8 + g;
                if (row < rows) {
                    const int slot = off + ts + row;
                    #pragma unroll
                    for (int nt = 0; nt < 8; nt++) {
                        const int col = ncol + nt*8 + tig*2;
                        float v0 = c[mm][nt][h*2]   + __ldg(&b1[e*1024+col]);
                        float v1 = c[mm][nt][h*2+1] + __ldg(&b1[e*1024+col+1]);
                        g_h1e[slot*1024 + col]   = fmaxf(v0, 0.f);
                        g_h1e[slot*1024 + col+1] = fmaxf(v1, 0.f);
                    }
                }
            }
    }
}

// ---------------- expert pass B (MMA): eo = gate*(h1 @ w2 + b2) ----------------
__global__ void __launch_bounds__(256) k_e2m(const float* __restrict__ b2) {
    const int e = blockIdx.y;
    const int cnt = g_counts[e];
    const int ts = blockIdx.x*64;
    if (ts >= cnt) return;
    const int off = g_offsets[e];
    const int rows = min(64, cnt - ts);
    extern __shared__ float sm[];
    float* smh = sm;
    float* sml = sm + 256*68;
    const int tid = threadIdx.x;
    const int lane = tid & 31, wrp = tid >> 5;
    const int g = lane >> 2, tig = lane & 3;
    const int mg = wrp >> 2, ng = wrp & 3;
    const float* Whi = g_e2hi + e*262144;
    const float* Wlo = g_e2lo + e*262144;

    float c[2][8][4];
    #pragma unroll
    for (int mm = 0; mm < 2; mm++)
        #pragma unroll
        for (int nt = 0; nt < 8; nt++)
            #pragma unroll
            for (int k = 0; k < 4; k++) c[mm][nt][k] = 0.f;

    for (int st = 0; st < 4; st++) {
        __syncthreads();
        for (int i = tid; i < 64*256; i += 256) {
            int rr = i >> 8, cc = i & 255;
            float v = (rr < rows) ? g_h1e[(off+ts+rr)*1024 + st*256 + cc] : 0.f;
            float h = tf32_hi(v);
            smh[cc*68 + rr] = h; sml[cc*68 + rr] = v - h;
        }
        __syncthreads();
        for (int k8 = 0; k8 < 256; k8 += 8) {
            unsigned ah[2][4], al[2][4];
            #pragma unroll
            for (int mm = 0; mm < 2; mm++) {
                const int mb = mg*32 + mm*16 + g;
                const int a0 = (k8+tig)*68 + mb;
                const int a1 = (k8+tig+4)*68 + mb;
                ah[mm][0] = __float_as_uint(smh[a0]);
                ah[mm][1] = __float_as_uint(smh[a0+8]);
                ah[mm][2] = __float_as_uint(smh[a1]);
                ah[mm][3] = __float_as_uint(smh[a1+8]);
                al[mm][0] = __float_as_uint(sml[a0]);
                al[mm][1] = __float_as_uint(sml[a0+8]);
                al[mm][2] = __float_as_uint(sml[a1]);
                al[mm][3] = __float_as_uint(sml[a1+8]);
            }
            #pragma unroll
            for (int nt = 0; nt < 8; nt++) {
                const int col = ng*64 + nt*8 + g;
                const int kb = (st*256 + k8 + tig)*256 + col;
                unsigned bh[2], bl[2];
                bh[0] = __float_as_uint(__ldg(&Whi[kb]));
                bh[1] = __float_as_uint(__ldg(&Whi[kb + 4*256]));
                bl[0] = __float_as_uint(__ldg(&Wlo[kb]));
                bl[1] = __float_as_uint(__ldg(&Wlo[kb + 4*256]));
                #pragma unroll
                for (int mm = 0; mm < 2; mm++) {
                    mma_tf32(c[mm][nt], ah[mm], bh);
                    mma_tf32(c[mm][nt], ah[mm], bl);
                    mma_tf32(c[mm][nt], al[mm], bh);
                }
            }
        }
    }
    #pragma unroll
    for (int mm = 0; mm < 2; mm++)
        #pragma unroll
        for (int h = 0; h < 2; h++) {
            const int row = mg*32 + mm*16 + h*8 + g;
            if (row < rows) {
                const int slot = off + ts + row;
                const float gt = g_list_g[slot];
                #pragma unroll
                for (int nt = 0; nt < 8; nt++) {
                    const int col = ng*64 + nt*8 + tig*2;
                    float v0 = c[mm][nt][h*2]   + __ldg(&b2[e*256+col]);
                    float v1 = c[mm][nt][h*2+1] + __ldg(&b2[e*256+col+1]);
                    g_eo[slot*256 + col]   = gt*v0;
                    g_eo[slot*256 + col+1] = gt*v1;
                }
            }
        }
}

// ---------------- combine + residual + LayerNorm ----------------
__global__ void __launch_bounds__(256) k_ln(const float* __restrict__ lng,
                                            const float* __restrict__ lnb) {
    const int b = blockIdx.x, tid = threadIdx.x;
    const int p0 = g_slotpos[b*2], p1 = g_slotpos[b*2+1];
    float y = g_eo[p0*256+tid] + g_eo[p1*256+tid] + g_feat[b*256+tid];
    __shared__ float red[16];
    __shared__ float mu_s, rstd_s;
    float s = y, s2 = y*y;
    #pragma unroll
    for (int o = 16; o > 0; o >>= 1) {
        s  += __shfl_xor_sync(0xffffffffu, s,  o);
        s2 += __shfl_xor_sync(0xffffffffu, s2, o);
    }
    if ((tid & 31) == 0) { red[tid>>5] = s; red[8 + (tid>>5)] = s2; }
    __syncthreads();
    if (tid == 0) {
        float S = 0.f, S2 = 0.f;
        #pragma unroll
        for (int i = 0; i < 8; i++) { S += red[i]; S2 += red[8+i]; }
        float mu = S/256.f;
        mu_s = mu;
        rstd_s = rsqrtf(S2/256.f - mu*mu + 1e-5f);
    }
    __syncthreads();
    g_y[b*256+tid] = (y - mu_s)*rstd_s*lng[tid] + lnb[tid];
}

// ---------------- output projection: [B,256] @ [256,1000] (FFMA) ----------------
__global__ void __launch_bounds__(256) k_out(const float* __restrict__ ow,
                                             const float* __restrict__ ob,
                                             float* __restrict__ out) {
    __shared__ float ys[32*256];
    const int bt = blockIdx.y*32, cb = blockIdx.x*256, tid = threadIdx.x;
    for (int i = tid; i < 8192; i += 256) ys[i] = g_y[bt*256 + i];
    __syncthreads();
    const int tx = tid & 63, ty = tid >> 6;
    const int c = cb + tx*4;
    bool v0 = c < NCLS, v1 = c+1 < NCLS, v2 = c+2 < NCLS, v3 = c+3 < NCLS;
    float acc[8][4];
    #pragma unroll
    for (int i = 0; i < 8; i++) { acc[i][0]=acc[i][1]=acc[i][2]=acc[i][3]=0.f; }
    for (int d = 0; d < 256; d++) {
        const float* wr = ow + d*NCLS;
        float w0 = v0 ? wr[c]   : 0.f;
        float w1 = v1 ? wr[c+1] : 0.f;
        float w2 = v2 ? wr[c+2] : 0.f;
        float w3 = v3 ? wr[c+3] : 0.f;
        #pragma unroll
        for (int i = 0; i < 8; i++) {
            float f = ys[(ty*8+i)*256 + d];
            acc[i][0] += f*w0; acc[i][1] += f*w1;
            acc[i][2] += f*w2; acc[i][3] += f*w3;
        }
    }
    float b0 = v0 ? ob[c] : 0.f, b1 = v1 ? ob[c+1] : 0.f;
    float b2 = v2 ? ob[c+2] : 0.f, b3 = v3 ? ob[c+3] : 0.f;
    #pragma unroll
    for (int i = 0; i < 8; i++) {
        float* o = out + (bt+ty*8+i)*NCLS;
        if (v0) o[c]   = acc[i][0] + b0;
        if (v1) o[c+1] = acc[i][1] + b1;
        if (v2) o[c+2] = acc[i][2] + b2;
        if (v3) o[c+3] = acc[i][3] + b3;
    }
}

// ---------------- launch ----------------
extern "C" void kernel_launch(void* const* d_in, const int* in_sizes, int n_in,
                              void* d_out, int out_size) {
    const float* x   = (const float*)d_in[0];
    const float* c1w = (const float*)d_in[1];
    const float* c1b = (const float*)d_in[2];
    const float* c2w = (const float*)d_in[3];
    const float* c2b = (const float*)d_in[4];
    const float* c3w = (const float*)d_in[5];
    const float* c3b = (const float*)d_in[6];
    const float* fcw = (const float*)d_in[7];
    const float* fcb = (const float*)d_in[8];
    const float* gw  = (const float*)d_in[9];
    const float* gb  = (const float*)d_in[10];
    const float* ew1 = (const float*)d_in[11];
    const float* eb1 = (const float*)d_in[12];
    const float* ew2 = (const float*)d_in[13];
    const float* eb2 = (const float*)d_in[14];
    const float* lng = (const float*)d_in[15];
    const float* lnb = (const float*)d_in[16];
    const float* ow  = (const float*)d_in[17];
    const float* ob  = (const float*)d_in[18];
    float* out = (float*)d_out;

    cudaFuncSetAttribute(k_conv2t, cudaFuncAttributeMaxDynamicSharedMemorySize, C2_SMEM);
    cudaFuncSetAttribute(k_conv3t, cudaFuncAttributeMaxDynamicSharedMemorySize, C3_SMEM);
    cudaFuncSetAttribute(k_e1m, cudaFuncAttributeMaxDynamicSharedMemorySize, GE_SMEM);
    cudaFuncSetAttribute(k_e2m, cudaFuncAttributeMaxDynamicSharedMemorySize, GE_SMEM);

    k_zero<<<1, 32>>>();
    k_wtrans<<<288, 256>>>(c2w, c3w);
    k_wprep<<<2048, 256>>>(ew1, ew2);
    k_conv1<<<BATCH/2, 512>>>(x, c1w, c1b);
    k_conv2t<<<BATCH, 256, C2_SMEM>>>(c2b);
    k_conv3t<<<BATCH/2, 256, C3_SMEM>>>(c3b);
    k_fc<<<BATCH/32, 256>>>(fcw, fcb);
    k_gate<<<BATCH/16, 256>>>(gw, gb);
    k_scan<<<1, 32>>>(out, out_size);
    k_scatter<<<BATCH*2/256, 256>>>();
    dim3 ge(128, 16);
    k_e1m<<<ge, 256, GE_SMEM>>>(eb1);
    k_e2m<<<ge, 256, GE_SMEM>>>(eb2);
    k_ln<<<BATCH, 256>>>(lng, lnb);
    dim3 go(4, BATCH/32);
    k_out<<<go, 256>>>(ow, ob, out);
}

// round 16
// speedup vs baseline: 1.0674x; 1.0104x over previous
#include <cuda_runtime.h>
#include <math.h>

#define BATCH 4096
#define NCLS  1000

// ---------------- scratch (device globals; no dynamic allocation) ----------------
__device__ float g_h1[BATCH*32*16*16];   // conv1 pooled out  [B,32,16,16]
__device__ float g_h2[BATCH*64*8*8];     // conv2 pooled out  [B,64,8,8]
__device__ float g_h3[BATCH*2048];       // conv3 pooled flat [B,2048]
__device__ float g_feat[BATCH*256];      // fc out            [B,256]
__device__ float g_y[BATCH*256];         // layernorm out     [B,256]
__device__ int   g_tidx[BATCH*2];        // top2 expert idx
__device__ float g_tg[BATCH*2];          // top2 gate weights
__device__ float g_gatesum[16];
__device__ int   g_counts[16];
__device__ int   g_offsets[16];
__device__ int   g_cursor[16];
__device__ int   g_list_b[BATCH*2];      // token id per grouped slot
__device__ float g_list_g[BATCH*2];      // gate weight per grouped slot
__device__ int   g_slotpos[BATCH*2];     // (b,k) -> grouped slot
__device__ float g_h1e[BATCH*2*1024];    // expert hidden per slot
__device__ float g_eo[BATCH*2*256];      // gate-scaled expert out per slot
// conv weights transposed to [tap][ci][oc], split hi/lo tf32
__device__ float g_wt2hi[9*32*64];
__device__ float g_wt2lo[9*32*64];
__device__ float g_wt3hi[9*64*128];
__device__ float g_wt3lo[9*64*128];
// expert weights split hi/lo (layout already [e][k][n])
__device__ float g_e1hi[16*262144];
__device__ float g_e1lo[16*262144];
__device__ float g_e2hi[16*262144];
__device__ float g_e2lo[16*262144];
// out weights split hi/lo, padded [256][1024]
__device__ float g_owhi[256*1024];
__device__ float g_owlo[256*1024];

// ---------------- tf32 helpers ----------------
__device__ __forceinline__ float tf32_hi(float x) {
    return __uint_as_float(__float_as_uint(x) & 0xFFFFE000u);
}

__device__ __forceinline__ void mma_tf32(float* c, const unsigned* a, const unsigned* b) {
    asm volatile(
        "mma.sync.aligned.m16n8k8.row.col.f32.tf32.tf32.f32 "
        "{%0,%1,%2,%3}, {%4,%5,%6,%7}, {%8,%9}, {%0,%1,%2,%3};"
        : "+f"(c[0]), "+f"(c[1]), "+f"(c[2]), "+f"(c[3])
        : "r"(a[0]), "r"(a[1]), "r"(a[2]), "r"(a[3]), "r"(b[0]), "r"(b[1]));
}

// ---------------- weight transpose (+ zero init): OIHW -> [tap][ci][oc], hi/lo split ----------------
__global__ void k_wtrans(const float* __restrict__ c2w, const float* __restrict__ c3w) {
    int idx = blockIdx.x*256 + threadIdx.x;
    if (blockIdx.x == 0 && threadIdx.x < 16) {
        g_gatesum[threadIdx.x] = 0.f; g_counts[threadIdx.x] = 0;
    }
    if (idx < 18432) {          // conv2: [64][32][9]
        int oc = idx / 288, rem = idx % 288;
        int ci = rem / 9, t = rem % 9;
        float v = c2w[idx];
        float hi = tf32_hi(v);
        int d = (t*32 + ci)*64 + oc;
        g_wt2hi[d] = hi; g_wt2lo[d] = v - hi;
    }
    if (idx < 73728) {          // conv3: [128][64][9]
        int oc = idx / 576, rem = idx % 576;
        int ci = rem / 9, t = rem % 9;
        float v = c3w[idx];
        float hi = tf32_hi(v);
        int d = (t*64 + ci)*128 + oc;
        g_wt3hi[d] = hi; g_wt3lo[d] = v - hi;
    }
}

// ---------------- expert weight hi/lo split ----------------
__global__ void k_wprep(const float* __restrict__ w1, const float* __restrict__ w2) {
    for (int i = blockIdx.x*256 + threadIdx.x; i < 16*262144; i += gridDim.x*256) {
        float v = w1[i]; float h = tf32_hi(v);
        g_e1hi[i] = h; g_e1lo[i] = v - h;
        v = w2[i]; h = tf32_hi(v);
        g_e2hi[i] = h; g_e2lo[i] = v - h;
    }
}

// ---------------- out weight hi/lo split (padded 1000->1024) ----------------
__global__ void k_wprep2(const float* __restrict__ ow) {
    int i = blockIdx.x*256 + threadIdx.x;
    if (i < 256*1024) {
        int k = i >> 10, n = i & 1023;
        float v = (n < NCLS) ? ow[k*NCLS + n] : 0.f;
        float h = tf32_hi(v);
        g_owhi[i] = h; g_owlo[i] = v - h;
    }
}

// ---------------- conv1: [B,3,32,32] -> pool -> relu -> [B,32,16,16] ----------------
// 2 img/block; reg-capped to 64 so 2 CTAs/SM (32 warps) fit.
__global__ void __launch_bounds__(512, 2) k_conv1(const float* __restrict__ x,
                                                  const float* __restrict__ w,
                                                  const float* __restrict__ bias) {
    __shared__ float xs[2*3*34*34];
    __shared__ float ws[27*36];
    __shared__ float bs[32];
    const int b0 = blockIdx.x*2, tid = threadIdx.x;
    for (int i = tid; i < 2*3468; i += 512) xs[i] = 0.f;
    if (tid < 32) bs[tid] = bias[tid];
    __syncthreads();
    for (int i = tid; i < 2*3072; i += 512) {
        int img = i / 3072, rem = i % 3072;
        int ci = rem >> 10, r2 = rem & 1023;
        xs[img*3468 + ci*1156 + ((r2>>5)+1)*34 + (r2&31) + 1] = x[(b0+img)*3072 + rem];
    }
    for (int i = tid; i < 864; i += 512)
        ws[(i%27)*36 + (i/27)] = w[i];
    __syncthreads();

    const int img = tid >> 8, t = tid & 255;
    const int py = t >> 4, px = t & 15;
    const float* xsI = xs + img*3468;
    float* outp = g_h1 + (b0+img)*8192;
    for (int cb = 0; cb < 32; cb += 8) {
        float acc[8][4];
        #pragma unroll
        for (int j = 0; j < 8; j++) { acc[j][0]=acc[j][1]=acc[j][2]=acc[j][3]=0.f; }
        #pragma unroll
        for (int ci = 0; ci < 3; ci++) {
            #pragma unroll
            for (int ky = 0; ky < 3; ky++) {
                #pragma unroll
                for (int kx = 0; kx < 3; kx++) {
                    const int kk = ci*9 + ky*3 + kx;
                    float wv[8];
                    *(float4*)&wv[0] = *(const float4*)&ws[kk*36 + cb];
                    *(float4*)&wv[4] = *(const float4*)&ws[kk*36 + cb + 4];
                    float iv[4];
                    #pragma unroll
                    for (int dy = 0; dy < 2; dy++)
                        #pragma unroll
                        for (int dx = 0; dx < 2; dx++)
                            iv[dy*2+dx] = xsI[ci*1156 + (2*py+dy+ky)*34 + (2*px+dx+kx)];
                    #pragma unroll
                    for (int j = 0; j < 8; j++)
                        #pragma unroll
                        for (int p = 0; p < 4; p++)
                            acc[j][p] += wv[j]*iv[p];
                }
            }
        }
        #pragma unroll
        for (int j = 0; j < 8; j++) {
            float m = fmaxf(fmaxf(acc[j][0],acc[j][1]), fmaxf(acc[j][2],acc[j][3]));
            outp[(cb+j)*256 + t] = fmaxf(m + bs[cb+j], 0.f);
        }
    }
}

// ---------------- conv2: tensor-core 3xTF32 tap-GEMM ----------------
// 1 img/block, 256 thr = 8 warps = 2 ocg(32 oc) x 4 posg(4 rows y).
#define C2_SMEM (2*10368*4)
__global__ void __launch_bounds__(256) k_conv2t(const float* __restrict__ bias) {
    extern __shared__ float sm[];
    float* in_hi = sm;            // 32*18*18 padded
    float* in_lo = sm + 10368;
    const int b = blockIdx.x, tid = threadIdx.x;
    for (int i = tid; i < 10368; i += 256) { in_hi[i] = 0.f; in_lo[i] = 0.f; }
    __syncthreads();
    for (int i = tid; i < 8192; i += 256) {
        int ci = i >> 8, r2 = i & 255;
        float v = g_h1[b*8192 + i];
        float hi = tf32_hi(v);
        int d = ci*324 + ((r2>>4)+1)*18 + (r2&15) + 1;
        in_hi[d] = hi; in_lo[d] = v - hi;
    }
    __syncthreads();

    const int lane = tid & 31, wrp = tid >> 5;
    const int g = lane >> 2, tig = lane & 3;
    const int ocg = wrp >> 2, posg = wrp & 3;
    const int y0 = posg*4;
    const int ocm = ocg*32;

    float c[2][8][4];
    #pragma unroll
    for (int m = 0; m < 2; m++)
        #pragma unroll
        for (int nt = 0; nt < 8; nt++)
            #pragma unroll
            for (int k = 0; k < 4; k++) c[m][nt][k] = 0.f;

    const int blane = tig*324 + g;
    const int wlane = tig*64 + ocm + g;

    for (int c8 = 0; c8 < 32; c8 += 8) {
        #pragma unroll
        for (int t = 0; t < 9; t++) {
            const int ky = t/3, kx = t%3;
            const int wbase = (t*32 + c8)*64 + wlane;
            unsigned ah[2][4], al[2][4];
            #pragma unroll
            for (int m = 0; m < 2; m++) {
                const int wb = wbase + m*16;
                ah[m][0] = __float_as_uint(__ldg(&g_wt2hi[wb]));
                ah[m][1] = __float_as_uint(__ldg(&g_wt2hi[wb+8]));
                ah[m][2] = __float_as_uint(__ldg(&g_wt2hi[wb+256]));
                ah[m][3] = __float_as_uint(__ldg(&g_wt2hi[wb+264]));
                al[m][0] = __float_as_uint(__ldg(&g_wt2lo[wb]));
                al[m][1] = __float_as_uint(__ldg(&g_wt2lo[wb+8]));
                al[m][2] = __float_as_uint(__ldg(&g_wt2lo[wb+256]));
                al[m][3] = __float_as_uint(__ldg(&g_wt2lo[wb+264]));
            }
            const int bstep = c8*324 + blane + kx;
            #pragma unroll
            for (int nt = 0; nt < 8; nt++) {
                const int ry = nt >> 1, xh = nt & 1;
                const int ba = bstep + (y0+ry+ky)*18 + xh*8;
                unsigned bh[2], bl[2];
                bh[0] = __float_as_uint(in_hi[ba]);
                bh[1] = __float_as_uint(in_hi[ba + 4*324]);
                bl[0] = __float_as_uint(in_lo[ba]);
                bl[1] = __float_as_uint(in_lo[ba + 4*324]);
                #pragma unroll
                for (int m = 0; m < 2; m++) {
                    mma_tf32(c[m][nt], ah[m], bh);
                    mma_tf32(c[m][nt], ah[m], bl);
                    mma_tf32(c[m][nt], al[m], bh);
                }
            }
        }
    }

    float* outp = g_h2 + b*4096;
    #pragma unroll
    for (int m = 0; m < 2; m++) {
        #pragma unroll
        for (int h = 0; h < 2; h++) {
            const int oc = ocm + m*16 + h*8 + g;
            const float bv = __ldg(&bias[oc]);
            const int k0 = h*2;
            #pragma unroll
            for (int pr = 0; pr < 2; pr++) {
                #pragma unroll
                for (int xh = 0; xh < 2; xh++) {
                    const int nta = (2*pr)*2 + xh, ntb = nta + 2;
                    float v = fmaxf(fmaxf(c[m][nta][k0], c[m][nta][k0+1]),
                                    fmaxf(c[m][ntb][k0], c[m][ntb][k0+1]));
                    outp[oc*64 + (posg*2+pr)*8 + xh*4 + tig] = fmaxf(v + bv, 0.f);
                }
            }
        }
    }
}

// ---------------- conv3: tensor-core 3xTF32 tap-GEMM ----------------
// 2 img/block, 256 thr = 8 warps = 2 img x 4 ocg(32 oc); each warp: all 64 pos.
#define C3_SMEM (2*6400*2*4)
__global__ void __launch_bounds__(256) k_conv3t(const float* __restrict__ bias) {
    extern __shared__ float sm[];
    const int b0 = blockIdx.x*2, tid = threadIdx.x;
    for (int i = tid; i < 12800; i += 256) { sm[i] = 0.f; sm[12800 + i] = 0.f; }
    __syncthreads();
    for (int i = tid; i < 8192; i += 256) {
        int img = i >> 12, rem = i & 4095;
        int ci = rem >> 6, r2 = rem & 63;
        float v = g_h2[(b0+img)*4096 + rem];
        float hi = tf32_hi(v);
        int d = img*6400 + ci*100 + ((r2>>3)+1)*10 + (r2&7) + 1;
        sm[d] = hi; sm[12800 + d] = v - hi;
    }
    __syncthreads();

    const int lane = tid & 31, wrp = tid >> 5;
    const int g = lane >> 2, tig = lane & 3;
    const int img = wrp >> 2, ocg = wrp & 3;
    const int ocm = ocg*32;
    const float* in_hi = sm + img*6400;
    const float* in_lo = sm + 12800 + img*6400;

    float c[2][8][4];
    #pragma unroll
    for (int m = 0; m < 2; m++)
        #pragma unroll
        for (int nt = 0; nt < 8; nt++)
            #pragma unroll
            for (int k = 0; k < 4; k++) c[m][nt][k] = 0.f;

    const int blane = tig*100 + g;
    const int wlane = tig*128 + ocm + g;

    for (int c8 = 0; c8 < 64; c8 += 8) {
        #pragma unroll
        for (int t = 0; t < 9; t++) {
            const int ky = t/3, kx = t%3;
            const int wbase = (t*64 + c8)*128 + wlane;
            unsigned ah[2][4], al[2][4];
            #pragma unroll
            for (int m = 0; m < 2; m++) {
                const int wb = wbase + m*16;
                ah[m][0] = __float_as_uint(__ldg(&g_wt3hi[wb]));
                ah[m][1] = __float_as_uint(__ldg(&g_wt3hi[wb+8]));
                ah[m][2] = __float_as_uint(__ldg(&g_wt3hi[wb+512]));
                ah[m][3] = __float_as_uint(__ldg(&g_wt3hi[wb+520]));
                al[m][0] = __float_as_uint(__ldg(&g_wt3lo[wb]));
                al[m][1] = __float_as_uint(__ldg(&g_wt3lo[wb+8]));
                al[m][2] = __float_as_uint(__ldg(&g_wt3lo[wb+512]));
                al[m][3] = __float_as_uint(__ldg(&g_wt3lo[wb+520]));
            }
            const int bstep = c8*100 + blane + kx;
            #pragma unroll
            for (int nt = 0; nt < 8; nt++) {
                const int ba = bstep + (nt+ky)*10;
                unsigned bh[2], bl[2];
                bh[0] = __float_as_uint(in_hi[ba]);
                bh[1] = __float_as_uint(in_hi[ba + 4*100]);
                bl[0] = __float_as_uint(in_lo[ba]);
                bl[1] = __float_as_uint(in_lo[ba + 4*100]);
                #pragma unroll
                for (int m = 0; m < 2; m++) {
                    mma_tf32(c[m][nt], ah[m], bh);
                    mma_tf32(c[m][nt], ah[m], bl);
                    mma_tf32(c[m][nt], al[m], bh);
                }
            }
        }
    }

    float* outp = g_h3 + (b0+img)*2048;
    #pragma unroll
    for (int m = 0; m < 2; m++) {
        #pragma unroll
        for (int h = 0; h < 2; h++) {
            const int oc = ocm + m*16 + h*8 + g;
            const float bv = __ldg(&bias[oc]);
            const int k0 = h*2;
            #pragma unroll
            for (int py = 0; py < 4; py++) {
                float v = fmaxf(fmaxf(c[m][2*py][k0], c[m][2*py][k0+1]),
                                fmaxf(c[m][2*py+1][k0], c[m][2*py+1][k0+1]));
                outp[oc*16 + py*4 + tig] = fmaxf(v + bv, 0.f);
            }
        }
    }
}

// ---------------- fc: [B,2048] @ [2048,256] (FFMA) ----------------
__global__ void __launch_bounds__(256) k_fc(const float* __restrict__ fcw,
                                            const float* __restrict__ fcb) {
    __shared__ float hs[32*256];
    const int bt = blockIdx.x*32, tid = threadIdx.x;
    const int tx = tid & 63, ty = tid >> 6;
    float acc[8][4];
    #pragma unroll
    for (int i = 0; i < 8; i++) { acc[i][0]=acc[i][1]=acc[i][2]=acc[i][3]=0.f; }
    for (int kc = 0; kc < 8; kc++) {
        __syncthreads();
        for (int i = tid; i < 8192; i += 256) {
            int rr = i >> 8, c = i & 255;
            hs[i] = g_h3[(bt+rr)*2048 + kc*256 + c];
        }
        __syncthreads();
        for (int d = 0; d < 256; d++) {
            float4 wv = *(const float4*)&fcw[(kc*256+d)*256 + tx*4];
            #pragma unroll
            for (int i = 0; i < 8; i++) {
                float f = hs[(ty*8+i)*256 + d];
                acc[i][0] += f*wv.x; acc[i][1] += f*wv.y;
                acc[i][2] += f*wv.z; acc[i][3] += f*wv.w;
            }
        }
    }
    float4 bb = *(const float4*)&fcb[tx*4];
    #pragma unroll
    for (int i = 0; i < 8; i++) {
        float* o = &g_feat[(bt+ty*8+i)*256 + tx*4];
        o[0] = acc[i][0]+bb.x; o[1] = acc[i][1]+bb.y;
        o[2] = acc[i][2]+bb.z; o[3] = acc[i][3]+bb.w;
    }
}

// ---------------- gate: logits, top-2, softmax, counts ----------------
__global__ void __launch_bounds__(256) k_gate(const float* __restrict__ gw,
                                              const float* __restrict__ gb) {
    __shared__ float fs[16*256];
    __shared__ float ls[16*17];
    const int b0 = blockIdx.x*16, tid = threadIdx.x;
    for (int i = tid; i < 4096; i += 256) fs[i] = g_feat[b0*256 + i];
    __syncthreads();
    const int t = tid >> 4, e = tid & 15;
    float acc = gb[e];
    for (int d = 0; d < 256; d++) acc += fs[t*256+d]*__ldg(&gw[d*16+e]);
    ls[t*17+e] = acc;
    __syncthreads();
    if (e == 0) {
        const float* l = &ls[t*17];
        int i1 = 0; float v1 = l[0];
        #pragma unroll
        for (int i = 1; i < 16; i++) if (l[i] > v1) { v1 = l[i]; i1 = i; }
        int i2 = -1; float v2 = -1e30f;
        #pragma unroll
        for (int i = 0; i < 16; i++) if (i != i1 && l[i] > v2) { v2 = l[i]; i2 = i; }
        float e2 = expf(v2 - v1);
        float inv = 1.0f/(1.0f + e2);
        float g1 = inv, g2 = e2*inv;
        int b = b0 + t;
        g_tidx[b*2] = i1;  g_tidx[b*2+1] = i2;
        g_tg[b*2]   = g1;  g_tg[b*2+1]   = g2;
        atomicAdd(&g_gatesum[i1], g1);
        atomicAdd(&g_gatesum[i2], g2);
        atomicAdd(&g_counts[i1], 1);
        atomicAdd(&g_counts[i2], 1);
    }
}

// ---------------- fused scan (offsets + lb_loss) + scatter ----------------
__global__ void __launch_bounds__(256) k_scan2(float* d_out, int out_size) {
    const int tid = threadIdx.x;
    if (tid == 0) {
        int off = 0;
        for (int e = 0; e < 16; e++) {
            g_offsets[e] = off; g_cursor[e] = off; off += g_counts[e];
        }
        float loss = 0.f;
        for (int e = 0; e < 16; e++) {
            float di = g_gatesum[e] / (float)BATCH;
            loss += di * logf(di + 1e-8f);
        }
        if (out_size > BATCH*NCLS) d_out[BATCH*NCLS] = loss;
    }
    __syncthreads();
    for (int s = tid; s < BATCH*2; s += 256) {
        int e = g_tidx[s];
        int pos = atomicAdd(&g_cursor[e], 1);
        g_list_b[pos] = s >> 1;
        g_list_g[pos] = g_tg[s];
        g_slotpos[s] = pos;
    }
}

// ---------------- expert pass A (MMA): h1 = relu(feat @ w1 + b1) ----------------
#define GE_SMEM (2*256*68*4)
__global__ void __launch_bounds__(256) k_e1m(const float* __restrict__ b1) {
    const int e = blockIdx.y;
    const int cnt = g_counts[e];
    const int ts = blockIdx.x*64;
    if (ts >= cnt) return;
    const int off = g_offsets[e];
    const int rows = min(64, cnt - ts);
    extern __shared__ float sm[];
    float* smh = sm;
    float* sml = sm + 256*68;
    const int tid = threadIdx.x;
    for (int i = tid; i < 64*256; i += 256) {
        int rr = i >> 8, cc = i & 255;
        float v = (rr < rows) ? g_feat[g_list_b[off+ts+rr]*256 + cc] : 0.f;
        float h = tf32_hi(v);
        smh[cc*68 + rr] = h; sml[cc*68 + rr] = v - h;
    }
    __syncthreads();
    const int lane = tid & 31, wrp = tid >> 5;
    const int g = lane >> 2, tig = lane & 3;
    const int mg = wrp >> 2, ng = wrp & 3;
    const float* Whi = g_e1hi + e*262144;
    const float* Wlo = g_e1lo + e*262144;

    for (int np = 0; np < 4; np++) {
        const int ncol = np*256 + ng*64;
        float c[2][8][4];
        #pragma unroll
        for (int mm = 0; mm < 2; mm++)
            #pragma unroll
            for (int nt = 0; nt < 8; nt++)
                #pragma unroll
                for (int k = 0; k < 4; k++) c[mm][nt][k] = 0.f;
        for (int k8 = 0; k8 < 256; k8 += 8) {
            unsigned ah[2][4], al[2][4];
            #pragma unroll
            for (int mm = 0; mm < 2; mm++) {
                const int mb = mg*32 + mm*16 + g;
                const int a0 = (k8+tig)*68 + mb;
                const int a1 = (k8+tig+4)*68 + mb;
                ah[mm][0] = __float_as_uint(smh[a0]);
                ah[mm][1] = __float_as_uint(smh[a0+8]);
                ah[mm][2] = __float_as_uint(smh[a1]);
                ah[mm][3] = __float_as_uint(smh[a1+8]);
                al[mm][0] = __float_as_uint(sml[a0]);
                al[mm][1] = __float_as_uint(sml[a0+8]);
                al[mm][2] = __float_as_uint(sml[a1]);
                al[mm][3] = __float_as_uint(sml[a1+8]);
            }
            #pragma unroll
            for (int nt = 0; nt < 8; nt++) {
                const int col = ncol + nt*8 + g;
                const int kb = (k8+tig)*1024 + col;
                unsigned bh[2], bl[2];
                bh[0] = __float_as_uint(__ldg(&Whi[kb]));
                bh[1] = __float_as_uint(__ldg(&Whi[kb + 4*1024]));
                bl[0] = __float_as_uint(__ldg(&Wlo[kb]));
                bl[1] = __float_as_uint(__ldg(&Wlo[kb + 4*1024]));
                #pragma unroll
                for (int mm = 0; mm < 2; mm++) {
                    mma_tf32(c[mm][nt], ah[mm], bh);
                    mma_tf32(c[mm][nt], ah[mm], bl);
                    mma_tf32(c[mm][nt], al[mm], bh);
                }
            }
        }
        #pragma unroll
        for (int mm = 0; mm < 2; mm++)
            #pragma unroll
            for (int h = 0; h < 2; h++) {
                const int row = mg*32 + mm*16 + h*8 + g;
                if (row < rows) {
                    const int slot = off + ts + row;
                    #pragma unroll
                    for (int nt = 0; nt < 8; nt++) {
                        const int col = ncol + nt*8 + tig*2;
                        float v0 = c[mm][nt][h*2]   + __ldg(&b1[e*1024+col]);
                        float v1 = c[mm][nt][h*2+1] + __ldg(&b1[e*1024+col+1]);
                        g_h1e[slot*1024 + col]   = fmaxf(v0, 0.f);
                        g_h1e[slot*1024 + col+1] = fmaxf(v1, 0.f);
                    }
                }
            }
    }
}

// ---------------- expert pass B (MMA): eo = gate*(h1 @ w2 + b2) ----------------
__global__ void __launch_bounds__(256) k_e2m(const float* __restrict__ b2) {
    const int e = blockIdx.y;
    const int cnt = g_counts[e];
    const int ts = blockIdx.x*64;
    if (ts >= cnt) return;
    const int off = g_offsets[e];
    const int rows = min(64, cnt - ts);
    extern __shared__ float sm[];
    float* smh = sm;
    float* sml = sm + 256*68;
    const int tid = threadIdx.x;
    const int lane = tid & 31, wrp = tid >> 5;
    const int g = lane >> 2, tig = lane & 3;
    const int mg = wrp >> 2, ng = wrp & 3;
    const float* Whi = g_e2hi + e*262144;
    const float* Wlo = g_e2lo + e*262144;

    float c[2][8][4];
    #pragma unroll
    for (int mm = 0; mm < 2; mm++)
        #pragma unroll
        for (int nt = 0; nt < 8; nt++)
            #pragma unroll
            for (int k = 0; k < 4; k++) c[mm][nt][k] = 0.f;

    for (int st = 0; st < 4; st++) {
        __syncthreads();
        for (int i = tid; i < 64*256; i += 256) {
            int rr = i >> 8, cc = i & 255;
            float v = (rr < rows) ? g_h1e[(off+ts+rr)*1024 + st*256 + cc] : 0.f;
            float h = tf32_hi(v);
            smh[cc*68 + rr] = h; sml[cc*68 + rr] = v - h;
        }
        __syncthreads();
        for (int k8 = 0; k8 < 256; k8 += 8) {
            unsigned ah[2][4], al[2][4];
            #pragma unroll
            for (int mm = 0; mm < 2; mm++) {
                const int mb = mg*32 + mm*16 + g;
                const int a0 = (k8+tig)*68 + mb;
                const int a1 = (k8+tig+4)*68 + mb;
                ah[mm][0] = __float_as_uint(smh[a0]);
                ah[mm][1] = __float_as_uint(smh[a0+8]);
                ah[mm][2] = __float_as_uint(smh[a1]);
                ah[mm][3] = __float_as_uint(smh[a1+8]);
                al[mm][0] = __float_as_uint(sml[a0]);
                al[mm][1] = __float_as_uint(sml[a0+8]);
                al[mm][2] = __float_as_uint(sml[a1]);
                al[mm][3] = __float_as_uint(sml[a1+8]);
            }
            #pragma unroll
            for (int nt = 0; nt < 8; nt++) {
                const int col = ng*64 + nt*8 + g;
                const int kb = (st*256 + k8 + tig)*256 + col;
                unsigned bh[2], bl[2];
                bh[0] = __float_as_uint(__ldg(&Whi[kb]));
                bh[1] = __float_as_uint(__ldg(&Whi[kb + 4*256]));
                bl[0] = __float_as_uint(__ldg(&Wlo[kb]));
                bl[1] = __float_as_uint(__ldg(&Wlo[kb + 4*256]));
                #pragma unroll
                for (int mm = 0; mm < 2; mm++) {
                    mma_tf32(c[mm][nt], ah[mm], bh);
                    mma_tf32(c[mm][nt], ah[mm], bl);
                    mma_tf32(c[mm][nt], al[mm], bh);
                }
            }
        }
    }
    #pragma unroll
    for (int mm = 0; mm < 2; mm++)
        #pragma unroll
        for (int h = 0; h < 2; h++) {
            const int row = mg*32 + mm*16 + h*8 + g;
            if (row < rows) {
                const int slot = off + ts + row;
                const float gt = g_list_g[slot];
                #pragma unroll
                for (int nt = 0; nt < 8; nt++) {
                    const int col = ng*64 + nt*8 + tig*2;
                    float v0 = c[mm][nt][h*2]   + __ldg(&b2[e*256+col]);
                    float v1 = c[mm][nt][h*2+1] + __ldg(&b2[e*256+col+1]);
                    g_eo[slot*256 + col]   = gt*v0;
                    g_eo[slot*256 + col+1] = gt*v1;
                }
            }
        }
}

// ---------------- combine + residual + LayerNorm ----------------
__global__ void __launch_bounds__(256) k_ln(const float* __restrict__ lng,
                                            const float* __restrict__ lnb) {
    const int b = blockIdx.x, tid = threadIdx.x;
    const int p0 = g_slotpos[b*2], p1 = g_slotpos[b*2+1];
    float y = g_eo[p0*256+tid] + g_eo[p1*256+tid] + g_feat[b*256+tid];
    __shared__ float red[16];
    __shared__ float mu_s, rstd_s;
    float s = y, s2 = y*y;
    #pragma unroll
    for (int o = 16; o > 0; o >>= 1) {
        s  += __shfl_xor_sync(0xffffffffu, s,  o);
        s2 += __shfl_xor_sync(0xffffffffu, s2, o);
    }
    if ((tid & 31) == 0) { red[tid>>5] = s; red[8 + (tid>>5)] = s2; }
    __syncthreads();
    if (tid == 0) {
        float S = 0.f, S2 = 0.f;
        #pragma unroll
        for (int i = 0; i < 8; i++) { S += red[i]; S2 += red[8+i]; }
        float mu = S/256.f;
        mu_s = mu;
        rstd_s = rsqrtf(S2/256.f - mu*mu + 1e-5f);
    }
    __syncthreads();
    g_y[b*256+tid] = (y - mu_s)*rstd_s*lng[tid] + lnb[tid];
}

// ---------------- output projection (MMA): out = y @ ow + ob ----------------
// grid (64, 4): 64-token tiles x 4 N-passes of 256 cols; K=256 single stage.
__global__ void __launch_bounds__(256) k_outm(const float* __restrict__ ob,
                                              float* __restrict__ out) {
    const int bt = blockIdx.x*64;
    const int np = blockIdx.y;
    extern __shared__ float sm[];
    float* smh = sm;
    float* sml = sm + 256*68;
    const int tid = threadIdx.x;
    for (int i = tid; i < 64*256; i += 256) {
        int rr = i >> 8, cc = i & 255;
        float v = g_y[(bt+rr)*256 + cc];
        float h = tf32_hi(v);
        smh[cc*68 + rr] = h; sml[cc*68 + rr] = v - h;
    }
    __syncthreads();
    const int lane = tid & 31, wrp = tid >> 5;
    const int g = lane >> 2, tig = lane & 3;
    const int mg = wrp >> 2, ng = wrp & 3;

    const int ncol = np*256 + ng*64;
    float c[2][8][4];
    #pragma unroll
    for (int mm = 0; mm < 2; mm++)
        #pragma unroll
        for (int nt = 0; nt < 8; nt++)
            #pragma unroll
            for (int k = 0; k < 4; k++) c[mm][nt][k] = 0.f;
    for (int k8 = 0; k8 < 256; k8 += 8) {
        unsigned ah[2][4], al[2][4];
        #pragma unroll
        for (int mm = 0; mm < 2; mm++) {
            const int mb = mg*32 + mm*16 + g;
            const int a0 = (k8+tig)*68 + mb;
            const int a1 = (k8+tig+4)*68 + mb;
            ah[mm][0] = __float_as_uint(smh[a0]);
            ah[mm][1] = __float_as_uint(smh[a0+8]);
            ah[mm][2] = __float_as_uint(smh[a1]);
            ah[mm][3] = __float_as_uint(smh[a1+8]);
            al[mm][0] = __float_as_uint(sml[a0]);
            al[mm][1] = __float_as_uint(sml[a0+8]);
            al[mm][2] = __float_as_uint(sml[a1]);
            al[mm][3] = __float_as_uint(sml[a1+8]);
        }
        #pragma unroll
        for (int nt = 0; nt < 8; nt++) {
            const int col = ncol + nt*8 + g;
            const int kb = (k8+tig)*1024 + col;
            unsigned bh[2], bl[2];
            bh[0] = __float_as_uint(__ldg(&g_owhi[kb]));
            bh[1] = __float_as_uint(__ldg(&g_owhi[kb + 4*1024]));
            bl[0] = __float_as_uint(__ldg(&g_owlo[kb]));
            bl[1] = __float_as_uint(__ldg(&g_owlo[kb + 4*1024]));
            #pragma unroll
            for (int mm = 0; mm < 2; mm++) {
                mma_tf32(c[mm][nt], ah[mm], bh);
                mma_tf32(c[mm][nt], ah[mm], bl);
                mma_tf32(c[mm][nt], al[mm], bh);
            }
        }
    }
    #pragma unroll
    for (int mm = 0; mm < 2; mm++)
        #pragma unroll
        for (int h = 0; h < 2; h++) {
            const int row = mg*32 + mm*16 + h*8 + g;
            float* orow = out + (bt+row)*NCLS;
            #pragma unroll
            for (int nt = 0; nt < 8; nt++) {
                const int col = ncol + nt*8 + tig*2;
                if (col < NCLS)
                    orow[col]   = c[mm][nt][h*2]   + __ldg(&ob[col]);
                if (col+1 < NCLS)
                    orow[col+1] = c[mm][nt][h*2+1] + __ldg(&ob[col+1]);
            }
        }
}

// ---------------- launch ----------------
extern "C" void kernel_launch(void* const* d_in, const int* in_sizes, int n_in,
                              void* d_out, int out_size) {
    const float* x   = (const float*)d_in[0];
    const float* c1w = (const float*)d_in[1];
    const float* c1b = (const float*)d_in[2];
    const float* c2w = (const float*)d_in[3];
    const float* c2b = (const float*)d_in[4];
    const float* c3w = (const float*)d_in[5];
    const float* c3b = (const float*)d_in[6];
    const float* fcw = (const float*)d_in[7];
    const float* fcb = (const float*)d_in[8];
    const float* gw  = (const float*)d_in[9];
    const float* gb  = (const float*)d_in[10];
    const float* ew1 = (const float*)d_in[11];
    const float* eb1 = (const float*)d_in[12];
    const float* ew2 = (const float*)d_in[13];
    const float* eb2 = (const float*)d_in[14];
    const float* lng = (const float*)d_in[15];
    const float* lnb = (const float*)d_in[16];
    const float* ow  = (const float*)d_in[17];
    const float* ob  = (const float*)d_in[18];
    float* out = (float*)d_out;

    cudaFuncSetAttribute(k_conv2t, cudaFuncAttributeMaxDynamicSharedMemorySize, C2_SMEM);
    cudaFuncSetAttribute(k_conv3t, cudaFuncAttributeMaxDynamicSharedMemorySize, C3_SMEM);
    cudaFuncSetAttribute(k_e1m, cudaFuncAttributeMaxDynamicSharedMemorySize, GE_SMEM);
    cudaFuncSetAttribute(k_e2m, cudaFuncAttributeMaxDynamicSharedMemorySize, GE_SMEM);
    cudaFuncSetAttribute(k_outm, cudaFuncAttributeMaxDynamicSharedMemorySize, GE_SMEM);

    k_wtrans<<<288, 256>>>(c2w, c3w);
    k_wprep<<<2048, 256>>>(ew1, ew2);
    k_wprep2<<<1024, 256>>>(ow);
    k_conv1<<<BATCH/2, 512>>>(x, c1w, c1b);
    k_conv2t<<<BATCH, 256, C2_SMEM>>>(c2b);
    k_conv3t<<<BATCH/2, 256, C3_SMEM>>>(c3b);
    k_fc<<<BATCH/32, 256>>>(fcw, fcb);
    k_gate<<<BATCH/16, 256>>>(gw, gb);
    k_scan2<<<1, 256>>>(out, out_size);
    dim3 ge(128, 16);
    k_e1m<<<ge, 256, GE_SMEM>>>(eb1);
    k_e2m<<<ge, 256, GE_SMEM>>>(eb2);
    k_ln<<<BATCH, 256>>>(lng, lnb);
    dim3 go(64, 4);
    k_outm<<<go, 256, GE_SMEM>>>(ob, out);
}